// round 1
// baseline (speedup 1.0000x reference)
#include <cuda_runtime.h>
#include <math.h>
#include <stdint.h>

#define NN 256
#define CC 128
#define CA 32
#define NH 4
#define NP (NN*NN)
#define QKV_COLS 384

static constexpr float LN_EPS_F = 1e-5f;
static constexpr float SCALE = 0.17677669529663689f;  // 1/sqrt(32)

// Scratch (device globals: allocation-free per harness rules)
__device__ float g_q[(size_t)NP * CA * NH];    // [(i*NH+h)*NN + j]*CA + ca
__device__ float g_k[(size_t)NP * CA * NH];
__device__ float g_v[(size_t)NP * CA * NH];
__device__ float g_gate[(size_t)CC * NP];      // [col][p], col = ca*NH + h
__device__ float g_bias[(size_t)NH * NN * NN]; // [h][k][j]
__device__ float g_attg[(size_t)CC * NP];      // [col][p]

// ---------------------------------------------------------------------------
// Phase 1: LayerNorm + qkv/gate/bias projections. 128 threads, 8 positions/blk.
// ---------------------------------------------------------------------------
__global__ __launch_bounds__(128) void phase1_kernel(
    const float* __restrict__ x, const float* __restrict__ ln_g, const float* __restrict__ ln_b,
    const float* __restrict__ Wqkv, const float* __restrict__ Wbias,
    const float* __restrict__ Wgate, const float* __restrict__ bgate)
{
    __shared__ float lnx[8][CC];
    __shared__ float stage[8][QKV_COLS];
    __shared__ float redS[8][4], redS2[8][4];

    const int t = threadIdx.x;
    const int p0 = blockIdx.x * 8;
    const int lane = t & 31, warp = t >> 5;

    float xv[8];
#pragma unroll
    for (int p = 0; p < 8; ++p) xv[p] = x[(size_t)(p0 + p) * CC + t];

#pragma unroll
    for (int p = 0; p < 8; ++p) {
        float s = xv[p], s2 = xv[p] * xv[p];
#pragma unroll
        for (int o = 16; o > 0; o >>= 1) {
            s  += __shfl_xor_sync(0xffffffffu, s,  o);
            s2 += __shfl_xor_sync(0xffffffffu, s2, o);
        }
        if (lane == 0) { redS[p][warp] = s; redS2[p][warp] = s2; }
    }
    __syncthreads();

    const float gmul = ln_g[t], badd = ln_b[t];
#pragma unroll
    for (int p = 0; p < 8; ++p) {
        float s  = redS[p][0] + redS[p][1] + redS[p][2] + redS[p][3];
        float s2 = redS2[p][0] + redS2[p][1] + redS2[p][2] + redS2[p][3];
        float mu  = s * (1.0f / CC);
        float var = s2 * (1.0f / CC) - mu * mu;
        lnx[p][t] = (xv[p] - mu) * rsqrtf(var + LN_EPS_F) * gmul + badd;
    }
    __syncthreads();

    // qkv: 3 columns per thread; lnx load shared across the 3 columns
    {
        float acc0[8] = {}, acc1[8] = {}, acc2[8] = {};
#pragma unroll 4
        for (int c = 0; c < CC; ++c) {
            float w0 = Wqkv[c * QKV_COLS + t];
            float w1 = Wqkv[c * QKV_COLS + 128 + t];
            float w2 = Wqkv[c * QKV_COLS + 256 + t];
#pragma unroll
            for (int p = 0; p < 8; ++p) {
                float xl = lnx[p][c];
                acc0[p] += xl * w0; acc1[p] += xl * w1; acc2[p] += xl * w2;
            }
        }
#pragma unroll
        for (int p = 0; p < 8; ++p) {
            stage[p][t] = acc0[p]; stage[p][128 + t] = acc1[p]; stage[p][256 + t] = acc2[p];
        }
    }
    __syncthreads();

    const int irow = p0 >> 8;
    const int j0 = p0 & 255;

    // flush q/k/v into [i][h][j][ca] layout (coalesced 256-float runs)
#pragma unroll
    for (int h = 0; h < NH; ++h) {
#pragma unroll
        for (int r = 0; r < 2; ++r) {
            int idx = r * 128 + t;
            int jj = idx >> 5, ca = idx & 31;
            size_t base = ((size_t)(irow * NH + h) * NN + (j0 + jj)) * CA + ca;
            g_q[base] = stage[jj][ca * 12 + h];
            g_k[base] = stage[jj][ca * 12 + NH + h];
            g_v[base] = stage[jj][ca * 12 + 2 * NH + h];
        }
    }

    // gate (col = t matches attg col index directly)
    {
        float acc[8] = {};
#pragma unroll 4
        for (int c = 0; c < CC; ++c) {
            float w = Wgate[c * CC + t];
#pragma unroll
            for (int p = 0; p < 8; ++p) acc[p] += lnx[p][c] * w;
        }
        float bg = bgate[t];
#pragma unroll
        for (int p = 0; p < 8; ++p) {
            float z = acc[p] + bg;
            g_gate[(size_t)t * NP + (p0 + p)] = 1.0f / (1.0f + __expf(-z));
        }
    }

    // bias: 32 threads, one (h, position) each
    if (t < 32) {
        int h = t & 3, p = t >> 2;
        float acc = 0.0f;
#pragma unroll 4
        for (int c = 0; c < CC; ++c) acc += lnx[p][c] * Wbias[c * NH + h];
        g_bias[((size_t)h * NN + irow) * NN + (j0 + p)] = acc;
    }
}

// ---------------------------------------------------------------------------
// Phase 2: per-(i,h) flash attention. 256 threads = one j each.
// k/v tiles in dynamic smem (64 KB); q and output accumulator in registers.
// ---------------------------------------------------------------------------
__global__ __launch_bounds__(256) void phase2_kernel()
{
    extern __shared__ float sm[];
    float* ksh = sm;              // NN*CA
    float* vsh = sm + NN * CA;    // NN*CA

    const int h = blockIdx.x;
    const int i = blockIdx.y;
    const int j = threadIdx.x;
    const size_t base = (size_t)(i * NH + h) * NN * CA;

    for (int idx = j; idx < NN * CA; idx += 256) {
        ksh[idx] = g_k[base + idx];
        vsh[idx] = g_v[base + idx];
    }
    __syncthreads();

    float q[CA];
    const float4* qp = (const float4*)(g_q + base + (size_t)j * CA);
#pragma unroll
    for (int c4 = 0; c4 < 8; ++c4) {
        float4 v4 = qp[c4];
        q[c4 * 4 + 0] = v4.x * SCALE;
        q[c4 * 4 + 1] = v4.y * SCALE;
        q[c4 * 4 + 2] = v4.z * SCALE;
        q[c4 * 4 + 3] = v4.w * SCALE;
    }

    float o[CA];
#pragma unroll
    for (int c = 0; c < CA; ++c) o[c] = 0.0f;
    float m = -1e30f, l = 0.0f;

    const float* brow = g_bias + (size_t)h * NN * NN + j;

    for (int kt = 0; kt < NN / 16; ++kt) {
        float s[16];
        float tm = -1e30f;
#pragma unroll
        for (int kk = 0; kk < 16; ++kk) {
            int k = kt * 16 + kk;
            const float* kr = ksh + k * CA;
            float acc = brow[(size_t)k * NN];
#pragma unroll
            for (int c = 0; c < CA; ++c) acc += q[c] * kr[c];
            s[kk] = acc;
            tm = fmaxf(tm, acc);
        }
        float nm = fmaxf(m, tm);
        float corr = __expf(m - nm);
        l *= corr;
#pragma unroll
        for (int c = 0; c < CA; ++c) o[c] *= corr;
#pragma unroll
        for (int kk = 0; kk < 16; ++kk) {
            float w = __expf(s[kk] - nm);
            l += w;
            const float* vr = vsh + (kt * 16 + kk) * CA;
#pragma unroll
            for (int c = 0; c < CA; ++c) o[c] += w * vr[c];
        }
        m = nm;
    }

    const float inv = 1.0f / l;
    const size_t p = (size_t)i * NN + j;
#pragma unroll
    for (int ca = 0; ca < CA; ++ca) {
        int col = ca * NH + h;
        g_attg[(size_t)col * NP + p] = o[ca] * inv * g_gate[(size_t)col * NP + p];
    }
}

// ---------------------------------------------------------------------------
// Phase 3: out = attg @ W_out + b_out. 128 threads, 16 positions per block.
// ---------------------------------------------------------------------------
__global__ __launch_bounds__(128) void phase3_kernel(
    const float* __restrict__ Wout, const float* __restrict__ bout,
    float* __restrict__ out)
{
    __shared__ float a[CC * 16];  // [col][p]
    const int t = threadIdx.x;
    const int p0 = blockIdx.x * 16;

    for (int idx = t; idx < CC * 16; idx += 128) {
        int col = idx >> 4, p = idx & 15;
        a[idx] = g_attg[(size_t)col * NP + p0 + p];
    }
    __syncthreads();

    float acc[16] = {};
#pragma unroll 4
    for (int col = 0; col < CC; ++col) {
        float w = Wout[col * CC + t];
#pragma unroll
        for (int p = 0; p < 16; ++p) acc[p] += a[col * 16 + p] * w;
    }
    const float bb = bout[t];
#pragma unroll
    for (int p = 0; p < 16; ++p)
        out[(size_t)(p0 + p) * CC + t] = acc[p] + bb;
}

// ---------------------------------------------------------------------------
extern "C" void kernel_launch(void* const* d_in, const int* in_sizes, int n_in,
                              void* d_out, int out_size)
{
    const float* x2d   = (const float*)d_in[0];
    const float* ln_g  = (const float*)d_in[1];
    const float* ln_b  = (const float*)d_in[2];
    const float* Wqkv  = (const float*)d_in[3];
    const float* Wbias = (const float*)d_in[4];
    const float* Wgate = (const float*)d_in[5];
    const float* bgate = (const float*)d_in[6];
    const float* Wout  = (const float*)d_in[7];
    const float* bout  = (const float*)d_in[8];
    float* out = (float*)d_out;

    const int smem2 = 2 * NN * CA * sizeof(float);  // 64 KB
    cudaFuncSetAttribute(phase2_kernel, cudaFuncAttributeMaxDynamicSharedMemorySize, smem2);

    phase1_kernel<<<NP / 8, 128>>>(x2d, ln_g, ln_b, Wqkv, Wbias, Wgate, bgate);
    phase2_kernel<<<dim3(NH, NN), 256, smem2>>>();
    phase3_kernel<<<NP / 16, 128>>>(Wout, bout, out);
}

// round 2
// speedup vs baseline: 1.5867x; 1.5867x over previous
#include <cuda_runtime.h>
#include <math.h>
#include <stdint.h>

#define NN 256
#define CC 128
#define CA 32
#define NH 4
#define NP (NN*NN)

static constexpr float LN_EPS_F = 1e-5f;
static constexpr float SCALE = 0.17677669529663689f;  // 1/sqrt(32)

// ---------------- scratch (device globals) ----------------
__device__ float g_lnx[(size_t)NP * CC];        // [p][c], tf32-rounded
__device__ float g_wbig[(size_t)CC * 512];      // [c][col], permuted, tf32-rounded
__device__ float g_bgate_p[128];                // permuted b_gate
__device__ float g_woutP[(size_t)CC * CC];      // [h*32+ca][out], tf32-rounded
__device__ float g_q[(size_t)NP * CA * NH];     // [i][h][j][ca]
__device__ float g_k[(size_t)NP * CA * NH];     // [i][h][k][ca]
__device__ float g_vT[(size_t)NP * CA * NH];    // [i][h][ca][k]
__device__ float g_gateP[(size_t)NP * CC];      // [p][h*32+ca]
__device__ float g_bias[(size_t)NH * NP];       // [h][p]
__device__ float g_attg[(size_t)NP * CC];       // [p][h*32+ca]

__device__ __forceinline__ float to_tf32(float x) {
    uint32_t u;
    asm("cvt.rna.tf32.f32 %0, %1;" : "=r"(u) : "f"(x));
    return __uint_as_float(u);
}

__device__ __forceinline__ void mma_tf32(float* d, uint32_t a0, uint32_t a1,
                                         uint32_t a2, uint32_t a3,
                                         uint32_t b0, uint32_t b1) {
    asm volatile(
        "mma.sync.aligned.m16n8k8.row.col.f32.tf32.tf32.f32 "
        "{%0,%1,%2,%3}, {%4,%5,%6,%7}, {%8,%9}, {%0,%1,%2,%3};\n"
        : "+f"(d[0]), "+f"(d[1]), "+f"(d[2]), "+f"(d[3])
        : "r"(a0), "r"(a1), "r"(a2), "r"(a3), "r"(b0), "r"(b1));
}

// ---------------------------------------------------------------------------
// LN + bias projection. 128 threads, 8 positions/block.
// ---------------------------------------------------------------------------
__global__ __launch_bounds__(128) void ln_kernel(
    const float* __restrict__ x, const float* __restrict__ ln_g, const float* __restrict__ ln_b,
    const float* __restrict__ Wbias)
{
    __shared__ float lnx[8][CC];
    __shared__ float redS[8][4], redS2[8][4];

    const int t = threadIdx.x;
    const int p0 = blockIdx.x * 8;
    const int lane = t & 31, warp = t >> 5;

    float xv[8];
#pragma unroll
    for (int p = 0; p < 8; ++p) xv[p] = x[(size_t)(p0 + p) * CC + t];

#pragma unroll
    for (int p = 0; p < 8; ++p) {
        float s = xv[p], s2 = xv[p] * xv[p];
#pragma unroll
        for (int o = 16; o > 0; o >>= 1) {
            s  += __shfl_xor_sync(0xffffffffu, s,  o);
            s2 += __shfl_xor_sync(0xffffffffu, s2, o);
        }
        if (lane == 0) { redS[p][warp] = s; redS2[p][warp] = s2; }
    }
    __syncthreads();

    const float gmul = ln_g[t], badd = ln_b[t];
#pragma unroll
    for (int p = 0; p < 8; ++p) {
        float s  = redS[p][0] + redS[p][1] + redS[p][2] + redS[p][3];
        float s2 = redS2[p][0] + redS2[p][1] + redS2[p][2] + redS2[p][3];
        float mu  = s * (1.0f / CC);
        float var = s2 * (1.0f / CC) - mu * mu;
        float v = (xv[p] - mu) * rsqrtf(var + LN_EPS_F) * gmul + badd;
        lnx[p][t] = v;
        g_lnx[(size_t)(p0 + p) * CC + t] = to_tf32(v);
    }
    __syncthreads();

    // bias: 32 threads, one (h, position) each; g_bias[h][p]
    if (t < 32) {
        int h = t & 3, p = t >> 2;
        float acc = 0.0f;
#pragma unroll 4
        for (int c = 0; c < CC; ++c) acc += lnx[p][c] * Wbias[c * NH + h];
        g_bias[(size_t)h * NP + p0 + p] = acc;
    }
}

// ---------------------------------------------------------------------------
// Weight prep: permute + tf32-round.
//   wbig col<384 : col=type*128+h*32+ca  <- Wqkv[c][ca*12+type*4+h]
//   wbig col>=384: col=384+h*32+ca       <- Wgate[c][ca*4+h]
//   woutP[h*32+ca][o] <- Wout[(ca*4+h)][o]
// ---------------------------------------------------------------------------
__global__ __launch_bounds__(512) void wprep_kernel(
    const float* __restrict__ Wqkv, const float* __restrict__ Wgate,
    const float* __restrict__ bgate, const float* __restrict__ Wout)
{
    const int t = threadIdx.x;
    int type, h, ca;
    if (t < 384) { type = t / 128; int r = t % 128; h = r / 32; ca = r % 32; }
    else         { int r = t - 384; h = r / 32; ca = r % 32; type = -1; }

    for (int c = 0; c < CC; ++c) {
        float v = (t < 384) ? Wqkv[c * 384 + ca * 12 + type * 4 + h]
                            : Wgate[c * 128 + ca * 4 + h];
        g_wbig[c * 512 + t] = to_tf32(v);
    }
    if (t < 128) {
        int hh = t / 32, cc = t % 32;
        g_bgate_p[t] = bgate[cc * 4 + hh];
        for (int o = 0; o < CC; ++o)
            g_woutP[t * CC + o] = to_tf32(Wout[(cc * 4 + hh) * CC + o]);
    }
}

// ---------------------------------------------------------------------------
// GEMM 65536x512x128 (qkv + gate) via tf32 mma. BM=128, BN=64, 256 thr.
// Grid (512, 8). ny<6: qkv epilogue; ny>=6: gate epilogue.
// ---------------------------------------------------------------------------
__global__ __launch_bounds__(256) void gemm512_kernel()
{
    extern __shared__ float sm[];
    float* As = sm;               // [128][132]
    float* Bs = sm + 128 * 132;   // [64 n][132 k]

    const int t = threadIdx.x;
    const int lane = t & 31, warp = t >> 5;
    const int wm = warp >> 1, wn = warp & 1;   // 4 x 2 warps over 128x64
    const int p0 = blockIdx.x * 128;
    const int n0 = blockIdx.y * 64;

    // load A (g_lnx rows p0..p0+127), float4
#pragma unroll
    for (int it = 0; it < 16; ++it) {
        int idx = it * 256 + t;                 // 4096 float4
        int r = idx >> 5, c4 = idx & 31;
        float4 v = *(const float4*)(g_lnx + (size_t)(p0 + r) * CC + c4 * 4);
        *(float4*)(As + r * 132 + c4 * 4) = v;
    }
    // load B transposed: Bs[n][k]
#pragma unroll
    for (int it = 0; it < 32; ++it) {
        int idx = it * 256 + t;                 // 8192 floats
        int k = idx >> 6, n = idx & 63;
        Bs[n * 132 + k] = g_wbig[(size_t)k * 512 + n0 + n];
    }
    __syncthreads();

    float acc[2][4][4];
#pragma unroll
    for (int mt = 0; mt < 2; ++mt)
#pragma unroll
        for (int nt = 0; nt < 4; ++nt)
#pragma unroll
            for (int e = 0; e < 4; ++e) acc[mt][nt][e] = 0.0f;

    const int lq = lane >> 2, lr = lane & 3;
#pragma unroll
    for (int k0 = 0; k0 < 128; k0 += 8) {
        uint32_t a[2][4], b[4][2];
#pragma unroll
        for (int mt = 0; mt < 2; ++mt) {
            int rb = wm * 32 + mt * 16;
            a[mt][0] = __float_as_uint(As[(rb + lq) * 132 + k0 + lr]);
            a[mt][1] = __float_as_uint(As[(rb + 8 + lq) * 132 + k0 + lr]);
            a[mt][2] = __float_as_uint(As[(rb + lq) * 132 + k0 + 4 + lr]);
            a[mt][3] = __float_as_uint(As[(rb + 8 + lq) * 132 + k0 + 4 + lr]);
        }
#pragma unroll
        for (int nt = 0; nt < 4; ++nt) {
            int nb = wn * 32 + nt * 8;
            b[nt][0] = __float_as_uint(Bs[(nb + lq) * 132 + k0 + lr]);
            b[nt][1] = __float_as_uint(Bs[(nb + lq) * 132 + k0 + 4 + lr]);
        }
#pragma unroll
        for (int mt = 0; mt < 2; ++mt)
#pragma unroll
            for (int nt = 0; nt < 4; ++nt)
                mma_tf32(acc[mt][nt], a[mt][0], a[mt][1], a[mt][2], a[mt][3],
                         b[nt][0], b[nt][1]);
    }
    __syncthreads();

    // stage C into smem (reuse As region): Cs[128][68]
    float* Cs = As;
#pragma unroll
    for (int mt = 0; mt < 2; ++mt)
#pragma unroll
        for (int nt = 0; nt < 4; ++nt) {
            int row = wm * 32 + mt * 16 + lq;
            int col = wn * 32 + nt * 8 + 2 * lr;
            *(float2*)(Cs + row * 68 + col)       = make_float2(acc[mt][nt][0], acc[mt][nt][1]);
            *(float2*)(Cs + (row + 8) * 68 + col) = make_float2(acc[mt][nt][2], acc[mt][nt][3]);
        }
    __syncthreads();

    const int i = p0 >> 8;
    const int j0 = p0 & 255;
    const int ny = blockIdx.y;

    if (ny < 6) {
        int type = ny >> 1;
        float* dst0 = (type == 0) ? g_q : (type == 1) ? g_k : g_vT;
#pragma unroll
        for (int half = 0; half < 2; ++half) {
            int h = (ny & 1) * 2 + half;
            if (type < 2) {
                // [j][ca] contiguous 128x32
                float* dst = dst0 + ((size_t)(i * NH + h) * NN + j0) * CA;
#pragma unroll
                for (int it = 0; it < 4; ++it) {
                    int idx = it * 256 + t;          // 1024 float4
                    int j = idx >> 3, c4 = idx & 7;
                    float4 v = *(float4*)(Cs + j * 68 + half * 32 + c4 * 4);
                    *(float4*)(dst + j * CA + c4 * 4) = v;
                }
            } else {
                // vT: [ca][j]
                float* dst = dst0 + ((size_t)(i * NH + h) * CA) * NN + j0;
#pragma unroll
                for (int it = 0; it < 16; ++it) {
                    int idx = it * 256 + t;          // 4096 floats
                    int ca = idx >> 7, j = idx & 127;
                    dst[(size_t)ca * NN + j] = Cs[j * 68 + half * 32 + ca];
                }
            }
        }
    } else {
        int gbase = (ny - 6) * 64;    // gate col base within 128
#pragma unroll
        for (int it = 0; it < 32; ++it) {
            int idx = it * 256 + t;              // 8192 floats
            int j = idx >> 6, c = idx & 63;
            float z = Cs[j * 68 + c] + g_bgate_p[gbase + c];
            g_gateP[(size_t)(p0 + j) * CC + gbase + c] = 1.0f / (1.0f + __expf(-z));
        }
    }
}

// ---------------------------------------------------------------------------
// Phase 2: per (jt, h, i): S = Q K^T (mma) -> smem, scalar softmax, O = P V^T
// (mma), gated epilogue. 256 threads (8 warps), 217KB smem.
// ---------------------------------------------------------------------------
#define QS_OFF 0
#define KS_OFF 4608            // 128*36
#define VT_OFF 13824           // + 256*36
#define S_OFF  22144           // + 32*260
#define L_OFF  55424           // + 128*260
#define P2_SMEM_BYTES 222208   // (55424+128)*4

__global__ __launch_bounds__(256, 1) void phase2_kernel()
{
    extern __shared__ float sm[];
    float* Qs  = sm + QS_OFF;   // [128][36]
    float* Ks  = sm + KS_OFF;   // [256][36]
    float* VTs = sm + VT_OFF;   // [32][260]
    float* Ss  = sm + S_OFF;    // [128][260]
    float* Ls  = sm + L_OFF;    // [128] (1/rowsum)

    const int jt = blockIdx.x, h = blockIdx.y, i = blockIdx.z;
    const int t = threadIdx.x;
    const int lane = t & 31, warp = t >> 5;
    const size_t base = (size_t)(i * NH + h) * NN * CA;

    // ---- loads (tf32-round into smem) ----
#pragma unroll
    for (int it = 0; it < 4; ++it) {                       // Q: 1024 f4
        int idx = it * 256 + t;
        int j = idx >> 3, c4 = idx & 7;
        float4 v = *(const float4*)(g_q + base + (size_t)(jt * 128 + j) * CA + c4 * 4);
        v.x = to_tf32(v.x * SCALE); v.y = to_tf32(v.y * SCALE);
        v.z = to_tf32(v.z * SCALE); v.w = to_tf32(v.w * SCALE);
        *(float4*)(Qs + j * 36 + c4 * 4) = v;
    }
#pragma unroll
    for (int it = 0; it < 8; ++it) {                       // K: 2048 f4
        int idx = it * 256 + t;
        int k = idx >> 3, c4 = idx & 7;
        float4 v = *(const float4*)(g_k + base + (size_t)k * CA + c4 * 4);
        v.x = to_tf32(v.x); v.y = to_tf32(v.y); v.z = to_tf32(v.z); v.w = to_tf32(v.w);
        *(float4*)(Ks + k * 36 + c4 * 4) = v;
    }
#pragma unroll
    for (int it = 0; it < 8; ++it) {                       // VT: 2048 f4
        int idx = it * 256 + t;
        int ca = idx >> 6, k4 = idx & 63;
        float4 v = *(const float4*)(g_vT + base + (size_t)ca * NN + k4 * 4);
        v.x = to_tf32(v.x); v.y = to_tf32(v.y); v.z = to_tf32(v.z); v.w = to_tf32(v.w);
        *(float4*)(VTs + ca * 260 + k4 * 4) = v;
    }
    __syncthreads();

    const int lq = lane >> 2, lr = lane & 3;

    // ---- QK^T: warps 2x4 over [128 j][256 k], warp tile 64x64 ----
    {
        const int wm = warp >> 2, wn = warp & 3;
        float acc[4][8][4];
#pragma unroll
        for (int mt = 0; mt < 4; ++mt)
#pragma unroll
            for (int nt = 0; nt < 8; ++nt)
#pragma unroll
                for (int e = 0; e < 4; ++e) acc[mt][nt][e] = 0.0f;

#pragma unroll
        for (int k0 = 0; k0 < 32; k0 += 8) {
            uint32_t a[4][4], b[8][2];
#pragma unroll
            for (int mt = 0; mt < 4; ++mt) {
                int rb = wm * 64 + mt * 16;
                a[mt][0] = __float_as_uint(Qs[(rb + lq) * 36 + k0 + lr]);
                a[mt][1] = __float_as_uint(Qs[(rb + 8 + lq) * 36 + k0 + lr]);
                a[mt][2] = __float_as_uint(Qs[(rb + lq) * 36 + k0 + 4 + lr]);
                a[mt][3] = __float_as_uint(Qs[(rb + 8 + lq) * 36 + k0 + 4 + lr]);
            }
#pragma unroll
            for (int nt = 0; nt < 8; ++nt) {
                int nb = wn * 64 + nt * 8;
                b[nt][0] = __float_as_uint(Ks[(nb + lq) * 36 + k0 + lr]);
                b[nt][1] = __float_as_uint(Ks[(nb + lq) * 36 + k0 + 4 + lr]);
            }
#pragma unroll
            for (int mt = 0; mt < 4; ++mt)
#pragma unroll
                for (int nt = 0; nt < 8; ++nt)
                    mma_tf32(acc[mt][nt], a[mt][0], a[mt][1], a[mt][2], a[mt][3],
                             b[nt][0], b[nt][1]);
        }
        // write S
#pragma unroll
        for (int mt = 0; mt < 4; ++mt)
#pragma unroll
            for (int nt = 0; nt < 8; ++nt) {
                int row = wm * 64 + mt * 16 + lq;
                int col = wn * 64 + nt * 8 + 2 * lr;
                *(float2*)(Ss + row * 260 + col)       = make_float2(acc[mt][nt][0], acc[mt][nt][1]);
                *(float2*)(Ss + (row + 8) * 260 + col) = make_float2(acc[mt][nt][2], acc[mt][nt][3]);
            }
    }
    __syncthreads();

    // ---- softmax over k (axis len 256); 2 threads per row ----
    {
        const int r = t >> 1, half = t & 1;
        const int jg = jt * 128 + r;
        const float* bias = g_bias + (size_t)h * NP + jg;
        float* srow = Ss + r * 260 + half * 128;

        float m = -1e30f;
#pragma unroll 4
        for (int k = 0; k < 128; ++k) {
            float s = srow[k] + bias[(size_t)(half * 128 + k) * NN];
            srow[k] = s;
            m = fmaxf(m, s);
        }
        m = fmaxf(m, __shfl_xor_sync(0xffffffffu, m, 1));
        float sum = 0.0f;
#pragma unroll 4
        for (int k = 0; k < 128; ++k) {
            float e = __expf(srow[k] - m);
            srow[k] = e;
            sum += e;
        }
        sum += __shfl_xor_sync(0xffffffffu, sum, 1);
        if (half == 0) Ls[r] = 1.0f / sum;
    }
    __syncthreads();

    // ---- O = P V^T: warp w owns rows w*16..+16; nt over 32 ca ----
    {
        float acc[4][4];
#pragma unroll
        for (int nt = 0; nt < 4; ++nt)
#pragma unroll
            for (int e = 0; e < 4; ++e) acc[nt][e] = 0.0f;

        const int rb = warp * 16;
#pragma unroll 4
        for (int k0 = 0; k0 < 256; k0 += 8) {
            uint32_t a0 = __float_as_uint(Ss[(rb + lq) * 260 + k0 + lr]);
            uint32_t a1 = __float_as_uint(Ss[(rb + 8 + lq) * 260 + k0 + lr]);
            uint32_t a2 = __float_as_uint(Ss[(rb + lq) * 260 + k0 + 4 + lr]);
            uint32_t a3 = __float_as_uint(Ss[(rb + 8 + lq) * 260 + k0 + 4 + lr]);
#pragma unroll
            for (int nt = 0; nt < 4; ++nt) {
                int nb = nt * 8;
                uint32_t b0 = __float_as_uint(VTs[(nb + lq) * 260 + k0 + lr]);
                uint32_t b1 = __float_as_uint(VTs[(nb + lq) * 260 + k0 + 4 + lr]);
                mma_tf32(acc[nt], a0, a1, a2, a3, b0, b1);
            }
        }
        // stage O (normalized) into Qs region: Os[128][36]
        float* Os = Qs;
        float inv0 = Ls[rb + lq], inv1 = Ls[rb + 8 + lq];
#pragma unroll
        for (int nt = 0; nt < 4; ++nt) {
            int col = nt * 8 + 2 * lr;
            *(float2*)(Os + (rb + lq) * 36 + col)     = make_float2(acc[nt][0] * inv0, acc[nt][1] * inv0);
            *(float2*)(Os + (rb + 8 + lq) * 36 + col) = make_float2(acc[nt][2] * inv1, acc[nt][3] * inv1);
        }
    }
    __syncthreads();

    // ---- gated epilogue: attg[p][h*32+ca] = O * gate ----
    {
        float* Os = Qs;
#pragma unroll
        for (int it = 0; it < 16; ++it) {
            int idx = it * 256 + t;           // 4096 floats
            int j = idx >> 5, ca = idx & 31;
            size_t p = (size_t)i * NN + jt * 128 + j;
            float v = Os[j * 36 + ca] * g_gateP[p * CC + h * 32 + ca];
            g_attg[p * CC + h * 32 + ca] = v;
        }
    }
}

// ---------------------------------------------------------------------------
// GEMM 65536x128x128: out = attg @ woutP + b_out. Same tiling as gemm512.
// Grid (512, 2).
// ---------------------------------------------------------------------------
__global__ __launch_bounds__(256) void gemm_out_kernel(
    const float* __restrict__ bout, float* __restrict__ out)
{
    extern __shared__ float sm[];
    float* As = sm;               // [128][132]
    float* Bs = sm + 128 * 132;   // [64][132]

    const int t = threadIdx.x;
    const int lane = t & 31, warp = t >> 5;
    const int wm = warp >> 1, wn = warp & 1;
    const int p0 = blockIdx.x * 128;
    const int n0 = blockIdx.y * 64;

#pragma unroll
    for (int it = 0; it < 16; ++it) {
        int idx = it * 256 + t;
        int r = idx >> 5, c4 = idx & 31;
        float4 v = *(const float4*)(g_attg + (size_t)(p0 + r) * CC + c4 * 4);
        *(float4*)(As + r * 132 + c4 * 4) = v;
    }
#pragma unroll
    for (int it = 0; it < 32; ++it) {
        int idx = it * 256 + t;
        int k = idx >> 6, n = idx & 63;
        Bs[n * 132 + k] = g_woutP[(size_t)k * CC + n0 + n];
    }
    __syncthreads();

    float acc[2][4][4];
#pragma unroll
    for (int mt = 0; mt < 2; ++mt)
#pragma unroll
        for (int nt = 0; nt < 4; ++nt)
#pragma unroll
            for (int e = 0; e < 4; ++e) acc[mt][nt][e] = 0.0f;

    const int lq = lane >> 2, lr = lane & 3;
#pragma unroll
    for (int k0 = 0; k0 < 128; k0 += 8) {
        uint32_t a[2][4], b[4][2];
#pragma unroll
        for (int mt = 0; mt < 2; ++mt) {
            int rb = wm * 32 + mt * 16;
            a[mt][0] = __float_as_uint(As[(rb + lq) * 132 + k0 + lr]);
            a[mt][1] = __float_as_uint(As[(rb + 8 + lq) * 132 + k0 + lr]);
            a[mt][2] = __float_as_uint(As[(rb + lq) * 132 + k0 + 4 + lr]);
            a[mt][3] = __float_as_uint(As[(rb + 8 + lq) * 132 + k0 + 4 + lr]);
        }
#pragma unroll
        for (int nt = 0; nt < 4; ++nt) {
            int nb = wn * 32 + nt * 8;
            b[nt][0] = __float_as_uint(Bs[(nb + lq) * 132 + k0 + lr]);
            b[nt][1] = __float_as_uint(Bs[(nb + lq) * 132 + k0 + 4 + lr]);
        }
#pragma unroll
        for (int mt = 0; mt < 2; ++mt)
#pragma unroll
            for (int nt = 0; nt < 4; ++nt)
                mma_tf32(acc[mt][nt], a[mt][0], a[mt][1], a[mt][2], a[mt][3],
                         b[nt][0], b[nt][1]);
    }
    __syncthreads();

    float* Cs = As;  // [128][68]
#pragma unroll
    for (int mt = 0; mt < 2; ++mt)
#pragma unroll
        for (int nt = 0; nt < 4; ++nt) {
            int row = wm * 32 + mt * 16 + lq;
            int col = wn * 32 + nt * 8 + 2 * lr;
            *(float2*)(Cs + row * 68 + col)       = make_float2(acc[mt][nt][0], acc[mt][nt][1]);
            *(float2*)(Cs + (row + 8) * 68 + col) = make_float2(acc[mt][nt][2], acc[mt][nt][3]);
        }
    __syncthreads();

#pragma unroll
    for (int it = 0; it < 8; ++it) {
        int idx = it * 256 + t;             // 2048 float4
        int j = idx >> 4, c4 = idx & 15;
        float4 v = *(float4*)(Cs + j * 68 + c4 * 4);
        float4 b = *(const float4*)(bout + n0 + c4 * 4);
        v.x += b.x; v.y += b.y; v.z += b.z; v.w += b.w;
        *(float4*)(out + (size_t)(p0 + j) * CC + n0 + c4 * 4) = v;
    }
}

// ---------------------------------------------------------------------------
extern "C" void kernel_launch(void* const* d_in, const int* in_sizes, int n_in,
                              void* d_out, int out_size)
{
    const float* x2d   = (const float*)d_in[0];
    const float* ln_g  = (const float*)d_in[1];
    const float* ln_b  = (const float*)d_in[2];
    const float* Wqkv  = (const float*)d_in[3];
    const float* Wbias = (const float*)d_in[4];
    const float* Wgate = (const float*)d_in[5];
    const float* bgate = (const float*)d_in[6];
    const float* Wout  = (const float*)d_in[7];
    const float* bout  = (const float*)d_in[8];
    float* out = (float*)d_out;

    const int smem_g = (128 * 132 + 64 * 132) * sizeof(float);  // 101376 B
    static bool attr_set = false;
    if (!attr_set) {
        cudaFuncSetAttribute(gemm512_kernel, cudaFuncAttributeMaxDynamicSharedMemorySize, smem_g);
        cudaFuncSetAttribute(gemm_out_kernel, cudaFuncAttributeMaxDynamicSharedMemorySize, smem_g);
        cudaFuncSetAttribute(phase2_kernel, cudaFuncAttributeMaxDynamicSharedMemorySize, P2_SMEM_BYTES);
        attr_set = true;
    }

    ln_kernel<<<NP / 8, 128>>>(x2d, ln_g, ln_b, Wbias);
    wprep_kernel<<<1, 512>>>(Wqkv, Wgate, bgate, Wout);
    gemm512_kernel<<<dim3(512, 8), 256, smem_g>>>();
    phase2_kernel<<<dim3(2, NH, NN), 256, P2_SMEM_BYTES>>>();
    gemm_out_kernel<<<dim3(512, 2), 256, smem_g>>>(bout, out);
}

// round 3
// speedup vs baseline: 2.7313x; 1.7214x over previous
#include <cuda_runtime.h>
#include <math.h>
#include <stdint.h>

#define NN 256
#define CC 128
#define CA 32
#define NH 4
#define NP (NN*NN)

static constexpr float LN_EPS_F = 1e-5f;
static constexpr float SCALE = 0.17677669529663689f;  // 1/sqrt(32)

// ---------------- scratch (device globals) ----------------
__device__ float g_lnx[(size_t)NP * CC];        // [p][c], tf32-rounded
__device__ float g_wbig[(size_t)CC * 512];      // [c][col], permuted, tf32-rounded
__device__ float g_bgate_p[128];                // permuted b_gate
__device__ float g_woutP[(size_t)CC * CC];      // [h*32+ca][out], tf32-rounded
__device__ float g_q[(size_t)NP * CA * NH];     // [i][h][j][ca]
__device__ float g_k[(size_t)NP * CA * NH];     // [i][h][k][ca]
__device__ float g_vT[(size_t)NP * CA * NH];    // [i][h][ca][k]
__device__ float g_gateP[(size_t)NP * CC];      // [p][h*32+ca]
__device__ float g_biasT[(size_t)NH * NP];      // [h][j][k]  (bias for key k, row j)
__device__ float g_attg[(size_t)NP * CC];       // [p][h*32+ca]

__device__ __forceinline__ float to_tf32(float x) {
    uint32_t u;
    asm("cvt.rna.tf32.f32 %0, %1;" : "=r"(u) : "f"(x));
    return __uint_as_float(u);
}

__device__ __forceinline__ void mma_tf32(float* d, uint32_t a0, uint32_t a1,
                                         uint32_t a2, uint32_t a3,
                                         uint32_t b0, uint32_t b1) {
    asm volatile(
        "mma.sync.aligned.m16n8k8.row.col.f32.tf32.tf32.f32 "
        "{%0,%1,%2,%3}, {%4,%5,%6,%7}, {%8,%9}, {%0,%1,%2,%3};\n"
        : "+f"(d[0]), "+f"(d[1]), "+f"(d[2]), "+f"(d[3])
        : "r"(a0), "r"(a1), "r"(a2), "r"(a3), "r"(b0), "r"(b1));
}

// ---------------------------------------------------------------------------
// LN + bias projection. 128 threads, 8 positions/block.
// ---------------------------------------------------------------------------
__global__ __launch_bounds__(128) void ln_kernel(
    const float* __restrict__ x, const float* __restrict__ ln_g, const float* __restrict__ ln_b,
    const float* __restrict__ Wbias)
{
    __shared__ float lnx[8][CC];
    __shared__ float redS[8][4], redS2[8][4];

    const int t = threadIdx.x;
    const int p0 = blockIdx.x * 8;
    const int lane = t & 31, warp = t >> 5;

    float xv[8];
#pragma unroll
    for (int p = 0; p < 8; ++p) xv[p] = x[(size_t)(p0 + p) * CC + t];

#pragma unroll
    for (int p = 0; p < 8; ++p) {
        float s = xv[p], s2 = xv[p] * xv[p];
#pragma unroll
        for (int o = 16; o > 0; o >>= 1) {
            s  += __shfl_xor_sync(0xffffffffu, s,  o);
            s2 += __shfl_xor_sync(0xffffffffu, s2, o);
        }
        if (lane == 0) { redS[p][warp] = s; redS2[p][warp] = s2; }
    }
    __syncthreads();

    const float gmul = ln_g[t], badd = ln_b[t];
#pragma unroll
    for (int p = 0; p < 8; ++p) {
        float s  = redS[p][0] + redS[p][1] + redS[p][2] + redS[p][3];
        float s2 = redS2[p][0] + redS2[p][1] + redS2[p][2] + redS2[p][3];
        float mu  = s * (1.0f / CC);
        float var = s2 * (1.0f / CC) - mu * mu;
        float v = (xv[p] - mu) * rsqrtf(var + LN_EPS_F) * gmul + badd;
        lnx[p][t] = v;
        g_lnx[(size_t)(p0 + p) * CC + t] = to_tf32(v);
    }
    __syncthreads();

    // bias: 32 threads, one (h, position) each.
    // Value computed at x-position (irow, j) is bias for key k=irow, attn-row j:
    // store g_biasT[h][j*NN + irow].
    if (t < 32) {
        int h = t & 3, p = t >> 2;
        float acc = 0.0f;
#pragma unroll 4
        for (int c = 0; c < CC; ++c) acc += lnx[p][c] * Wbias[c * NH + h];
        int irow = p0 >> 8, j0 = p0 & 255;
        g_biasT[(size_t)h * NP + (size_t)(j0 + p) * NN + irow] = acc;
    }
}

// ---------------------------------------------------------------------------
// Weight prep (parallelized): grid(CC) blocks, 512 threads: one c-row each.
// ---------------------------------------------------------------------------
__global__ __launch_bounds__(512) void wprep_kernel(
    const float* __restrict__ Wqkv, const float* __restrict__ Wgate)
{
    const int t = threadIdx.x, c = blockIdx.x;
    float v;
    if (t < 384) {
        int type = t / 128, r = t % 128, h = r / 32, ca = r % 32;
        v = Wqkv[c * 384 + ca * 12 + type * 4 + h];
    } else {
        int r = t - 384, h = r / 32, ca = r % 32;
        v = Wgate[c * 128 + ca * 4 + h];
    }
    g_wbig[c * 512 + t] = to_tf32(v);
}

__global__ __launch_bounds__(128) void wprep2_kernel(
    const float* __restrict__ bgate, const float* __restrict__ Wout)
{
    const int r = blockIdx.x;             // target row h*32+ca
    const int o = threadIdx.x;
    int h = r / 32, ca = r % 32;
    g_woutP[r * CC + o] = to_tf32(Wout[(ca * 4 + h) * CC + o]);
    if (o == 0) g_bgate_p[r] = bgate[ca * 4 + h];
}

// ---------------------------------------------------------------------------
// GEMM 65536x512x128 (qkv + gate) via tf32 mma. BM=128, BN=64, 256 thr.
// Grid (512, 8). ny<6: qkv epilogue; ny>=6: gate epilogue.
// ---------------------------------------------------------------------------
__global__ __launch_bounds__(256) void gemm512_kernel()
{
    extern __shared__ float sm[];
    float* As = sm;               // [128][132]
    float* Bs = sm + 128 * 132;   // [64 n][132 k]

    const int t = threadIdx.x;
    const int lane = t & 31, warp = t >> 5;
    const int wm = warp >> 1, wn = warp & 1;   // 4 x 2 warps over 128x64
    const int p0 = blockIdx.x * 128;
    const int n0 = blockIdx.y * 64;

#pragma unroll
    for (int it = 0; it < 16; ++it) {
        int idx = it * 256 + t;
        int r = idx >> 5, c4 = idx & 31;
        float4 v = *(const float4*)(g_lnx + (size_t)(p0 + r) * CC + c4 * 4);
        *(float4*)(As + r * 132 + c4 * 4) = v;
    }
#pragma unroll
    for (int it = 0; it < 32; ++it) {
        int idx = it * 256 + t;
        int k = idx >> 6, n = idx & 63;
        Bs[n * 132 + k] = g_wbig[(size_t)k * 512 + n0 + n];
    }
    __syncthreads();

    float acc[2][4][4];
#pragma unroll
    for (int mt = 0; mt < 2; ++mt)
#pragma unroll
        for (int nt = 0; nt < 4; ++nt)
#pragma unroll
            for (int e = 0; e < 4; ++e) acc[mt][nt][e] = 0.0f;

    const int lq = lane >> 2, lr = lane & 3;
#pragma unroll
    for (int k0 = 0; k0 < 128; k0 += 8) {
        uint32_t a[2][4], b[4][2];
#pragma unroll
        for (int mt = 0; mt < 2; ++mt) {
            int rb = wm * 32 + mt * 16;
            a[mt][0] = __float_as_uint(As[(rb + lq) * 132 + k0 + lr]);
            a[mt][1] = __float_as_uint(As[(rb + 8 + lq) * 132 + k0 + lr]);
            a[mt][2] = __float_as_uint(As[(rb + lq) * 132 + k0 + 4 + lr]);
            a[mt][3] = __float_as_uint(As[(rb + 8 + lq) * 132 + k0 + 4 + lr]);
        }
#pragma unroll
        for (int nt = 0; nt < 4; ++nt) {
            int nb = wn * 32 + nt * 8;
            b[nt][0] = __float_as_uint(Bs[(nb + lq) * 132 + k0 + lr]);
            b[nt][1] = __float_as_uint(Bs[(nb + lq) * 132 + k0 + 4 + lr]);
        }
#pragma unroll
        for (int mt = 0; mt < 2; ++mt)
#pragma unroll
            for (int nt = 0; nt < 4; ++nt)
                mma_tf32(acc[mt][nt], a[mt][0], a[mt][1], a[mt][2], a[mt][3],
                         b[nt][0], b[nt][1]);
    }
    __syncthreads();

    float* Cs = As;  // [128][68]
#pragma unroll
    for (int mt = 0; mt < 2; ++mt)
#pragma unroll
        for (int nt = 0; nt < 4; ++nt) {
            int row = wm * 32 + mt * 16 + lq;
            int col = wn * 32 + nt * 8 + 2 * lr;
            *(float2*)(Cs + row * 68 + col)       = make_float2(acc[mt][nt][0], acc[mt][nt][1]);
            *(float2*)(Cs + (row + 8) * 68 + col) = make_float2(acc[mt][nt][2], acc[mt][nt][3]);
        }
    __syncthreads();

    const int i = p0 >> 8;
    const int j0 = p0 & 255;
    const int ny = blockIdx.y;

    if (ny < 6) {
        int type = ny >> 1;
        float* dst0 = (type == 0) ? g_q : (type == 1) ? g_k : g_vT;
#pragma unroll
        for (int half = 0; half < 2; ++half) {
            int h = (ny & 1) * 2 + half;
            if (type < 2) {
                float* dst = dst0 + ((size_t)(i * NH + h) * NN + j0) * CA;
#pragma unroll
                for (int it = 0; it < 4; ++it) {
                    int idx = it * 256 + t;
                    int j = idx >> 3, c4 = idx & 7;
                    float4 v = *(float4*)(Cs + j * 68 + half * 32 + c4 * 4);
                    *(float4*)(dst + j * CA + c4 * 4) = v;
                }
            } else {
                float* dst = dst0 + ((size_t)(i * NH + h) * CA) * NN + j0;
#pragma unroll
                for (int it = 0; it < 16; ++it) {
                    int idx = it * 256 + t;
                    int ca = idx >> 7, j = idx & 127;
                    dst[(size_t)ca * NN + j] = Cs[j * 68 + half * 32 + ca];
                }
            }
        }
    } else {
        int gbase = (ny - 6) * 64;
#pragma unroll
        for (int it = 0; it < 32; ++it) {
            int idx = it * 256 + t;
            int j = idx >> 6, c = idx & 63;
            float z = Cs[j * 68 + c] + g_bgate_p[gbase + c];
            g_gateP[(size_t)(p0 + j) * CC + gbase + c] = 1.0f / (1.0f + __expf(-z));
        }
    }
}

// ---------------------------------------------------------------------------
// Phase 2: register-resident flash attention.
// Grid (2, NH, NN); 256 threads = 8 warps x 16 rows. K-tiles of 64 keys.
// ---------------------------------------------------------------------------
__global__ __launch_bounds__(256, 2) void phase2_kernel()
{
    __shared__ float Ks[64 * 36];   // [key][ca]
    __shared__ float Vts[32 * 68];  // [ca][key]

    const int jt = blockIdx.x, h = blockIdx.y, i = blockIdx.z;
    const int t = threadIdx.x, lane = t & 31, warp = t >> 5;
    const int lq = lane >> 2, lr = lane & 3;
    const size_t base = (size_t)(i * NH + h) * NN * CA;
    const int rb = jt * 128 + warp * 16;     // global attn-row base for this warp

    // Q fragments (scaled + tf32) — resident for the whole kernel
    uint32_t qa[4][4];
    {
        const float* Qp = g_q + base;
#pragma unroll
        for (int kk = 0; kk < 4; ++kk) {
            int k0 = kk * 8;
            qa[kk][0] = __float_as_uint(to_tf32(Qp[(rb + lq) * CA + k0 + lr] * SCALE));
            qa[kk][1] = __float_as_uint(to_tf32(Qp[(rb + 8 + lq) * CA + k0 + lr] * SCALE));
            qa[kk][2] = __float_as_uint(to_tf32(Qp[(rb + lq) * CA + k0 + 4 + lr] * SCALE));
            qa[kk][3] = __float_as_uint(to_tf32(Qp[(rb + 8 + lq) * CA + k0 + 4 + lr] * SCALE));
        }
    }

    float o[4][4];
#pragma unroll
    for (int nt = 0; nt < 4; ++nt)
#pragma unroll
        for (int e = 0; e < 4; ++e) o[nt][e] = 0.0f;
    float m0 = -1e30f, m1 = -1e30f, l0 = 0.0f, l1 = 0.0f;

    const float* biasRow0 = g_biasT + (size_t)h * NP + (size_t)(rb + lq) * NN;
    const float* biasRow1 = biasRow0 + 8 * NN;

    for (int kt = 0; kt < 4; ++kt) {
        // stage K tile [64][32] and Vt tile [32][64] (tf32-rounded)
#pragma unroll
        for (int it = 0; it < 2; ++it) {
            int id = it * 256 + t;
            int r = id >> 3, c4 = id & 7;
            float4 v = *(const float4*)(g_k + base + (size_t)(kt * 64 + r) * CA + c4 * 4);
            v.x = to_tf32(v.x); v.y = to_tf32(v.y); v.z = to_tf32(v.z); v.w = to_tf32(v.w);
            *(float4*)(Ks + r * 36 + c4 * 4) = v;
        }
#pragma unroll
        for (int it = 0; it < 2; ++it) {
            int id = it * 256 + t;
            int ca = id >> 4, c4 = id & 15;
            float4 v = *(const float4*)(g_vT + base + (size_t)ca * NN + kt * 64 + c4 * 4);
            v.x = to_tf32(v.x); v.y = to_tf32(v.y); v.z = to_tf32(v.z); v.w = to_tf32(v.w);
            *(float4*)(Vts + ca * 68 + c4 * 4) = v;
        }
        __syncthreads();

        // S = Q K^T  (16 x 64 per warp)
        float s[8][4];
#pragma unroll
        for (int nt = 0; nt < 8; ++nt)
#pragma unroll
            for (int e = 0; e < 4; ++e) s[nt][e] = 0.0f;

#pragma unroll
        for (int kk = 0; kk < 4; ++kk) {
            int k0 = kk * 8;
#pragma unroll
            for (int nt = 0; nt < 8; ++nt) {
                uint32_t b0 = __float_as_uint(Ks[(nt * 8 + lq) * 36 + k0 + lr]);
                uint32_t b1 = __float_as_uint(Ks[(nt * 8 + lq) * 36 + k0 + 4 + lr]);
                mma_tf32(s[nt], qa[kk][0], qa[kk][1], qa[kk][2], qa[kk][3], b0, b1);
            }
        }

        // + bias (exact fp32)
#pragma unroll
        for (int nt = 0; nt < 8; ++nt) {
            int kc = kt * 64 + nt * 8 + 2 * lr;
            float2 bA = *(const float2*)(biasRow0 + kc);
            float2 bB = *(const float2*)(biasRow1 + kc);
            s[nt][0] += bA.x; s[nt][1] += bA.y;
            s[nt][2] += bB.x; s[nt][3] += bB.y;
        }

        // online softmax (rows lq and lq+8)
        float tm0 = -1e30f, tm1 = -1e30f;
#pragma unroll
        for (int nt = 0; nt < 8; ++nt) {
            tm0 = fmaxf(tm0, fmaxf(s[nt][0], s[nt][1]));
            tm1 = fmaxf(tm1, fmaxf(s[nt][2], s[nt][3]));
        }
        tm0 = fmaxf(tm0, __shfl_xor_sync(0xffffffffu, tm0, 1));
        tm0 = fmaxf(tm0, __shfl_xor_sync(0xffffffffu, tm0, 2));
        tm1 = fmaxf(tm1, __shfl_xor_sync(0xffffffffu, tm1, 1));
        tm1 = fmaxf(tm1, __shfl_xor_sync(0xffffffffu, tm1, 2));

        float nm0 = fmaxf(m0, tm0), nm1 = fmaxf(m1, tm1);
        float c0 = __expf(m0 - nm0), c1 = __expf(m1 - nm1);
        m0 = nm0; m1 = nm1;
        l0 *= c0; l1 *= c1;
#pragma unroll
        for (int nt = 0; nt < 4; ++nt) {
            o[nt][0] *= c0; o[nt][1] *= c0;
            o[nt][2] *= c1; o[nt][3] *= c1;
        }

        float ps0 = 0.0f, ps1 = 0.0f;
#pragma unroll
        for (int nt = 0; nt < 8; ++nt) {
            s[nt][0] = __expf(s[nt][0] - m0);
            s[nt][1] = __expf(s[nt][1] - m0);
            s[nt][2] = __expf(s[nt][2] - m1);
            s[nt][3] = __expf(s[nt][3] - m1);
            ps0 += s[nt][0] + s[nt][1];
            ps1 += s[nt][2] + s[nt][3];
        }
        ps0 += __shfl_xor_sync(0xffffffffu, ps0, 1);
        ps0 += __shfl_xor_sync(0xffffffffu, ps0, 2);
        ps1 += __shfl_xor_sync(0xffffffffu, ps1, 1);
        ps1 += __shfl_xor_sync(0xffffffffu, ps1, 2);
        l0 += ps0; l1 += ps1;

        // O += P V^T: repack C-frag -> A-frag via shuffles, then mma
        const int src0 = (lane & ~3) | (lr >> 1);
        const int src2 = src0 + 2;
        const bool odd = lr & 1;
#pragma unroll
        for (int ks = 0; ks < 8; ++ks) {
            float t00 = __shfl_sync(0xffffffffu, s[ks][0], src0);
            float t01 = __shfl_sync(0xffffffffu, s[ks][1], src0);
            float t10 = __shfl_sync(0xffffffffu, s[ks][2], src0);
            float t11 = __shfl_sync(0xffffffffu, s[ks][3], src0);
            float u00 = __shfl_sync(0xffffffffu, s[ks][0], src2);
            float u01 = __shfl_sync(0xffffffffu, s[ks][1], src2);
            float u10 = __shfl_sync(0xffffffffu, s[ks][2], src2);
            float u11 = __shfl_sync(0xffffffffu, s[ks][3], src2);
            uint32_t a0 = __float_as_uint(odd ? t01 : t00);
            uint32_t a1 = __float_as_uint(odd ? t11 : t10);
            uint32_t a2 = __float_as_uint(odd ? u01 : u00);
            uint32_t a3 = __float_as_uint(odd ? u11 : u10);
#pragma unroll
            for (int nt = 0; nt < 4; ++nt) {
                uint32_t b0 = __float_as_uint(Vts[(nt * 8 + lq) * 68 + ks * 8 + lr]);
                uint32_t b1 = __float_as_uint(Vts[(nt * 8 + lq) * 68 + ks * 8 + 4 + lr]);
                mma_tf32(o[nt], a0, a1, a2, a3, b0, b1);
            }
        }
        __syncthreads();
    }

    // epilogue: normalize, gate, store
    const float inv0 = 1.0f / l0, inv1 = 1.0f / l1;
    const size_t p0r = (size_t)i * NN + rb + lq;
    const size_t p1r = p0r + 8;
#pragma unroll
    for (int nt = 0; nt < 4; ++nt) {
        int col = h * 32 + nt * 8 + 2 * lr;
        float2 g0 = *(const float2*)(g_gateP + p0r * CC + col);
        float2 g1 = *(const float2*)(g_gateP + p1r * CC + col);
        *(float2*)(g_attg + p0r * CC + col) =
            make_float2(o[nt][0] * inv0 * g0.x, o[nt][1] * inv0 * g0.y);
        *(float2*)(g_attg + p1r * CC + col) =
            make_float2(o[nt][2] * inv1 * g1.x, o[nt][3] * inv1 * g1.y);
    }
}

// ---------------------------------------------------------------------------
// GEMM 65536x128x128: out = attg @ woutP + b_out. Grid (512, 2).
// ---------------------------------------------------------------------------
__global__ __launch_bounds__(256) void gemm_out_kernel(
    const float* __restrict__ bout, float* __restrict__ out)
{
    extern __shared__ float sm[];
    float* As = sm;               // [128][132]
    float* Bs = sm + 128 * 132;   // [64][132]

    const int t = threadIdx.x;
    const int lane = t & 31, warp = t >> 5;
    const int wm = warp >> 1, wn = warp & 1;
    const int p0 = blockIdx.x * 128;
    const int n0 = blockIdx.y * 64;

#pragma unroll
    for (int it = 0; it < 16; ++it) {
        int idx = it * 256 + t;
        int r = idx >> 5, c4 = idx & 31;
        float4 v = *(const float4*)(g_attg + (size_t)(p0 + r) * CC + c4 * 4);
        *(float4*)(As + r * 132 + c4 * 4) = v;
    }
#pragma unroll
    for (int it = 0; it < 32; ++it) {
        int idx = it * 256 + t;
        int k = idx >> 6, n = idx & 63;
        Bs[n * 132 + k] = g_woutP[(size_t)k * CC + n0 + n];
    }
    __syncthreads();

    float acc[2][4][4];
#pragma unroll
    for (int mt = 0; mt < 2; ++mt)
#pragma unroll
        for (int nt = 0; nt < 4; ++nt)
#pragma unroll
            for (int e = 0; e < 4; ++e) acc[mt][nt][e] = 0.0f;

    const int lq = lane >> 2, lr = lane & 3;
#pragma unroll
    for (int k0 = 0; k0 < 128; k0 += 8) {
        uint32_t a[2][4], b[4][2];
#pragma unroll
        for (int mt = 0; mt < 2; ++mt) {
            int rb = wm * 32 + mt * 16;
            a[mt][0] = __float_as_uint(As[(rb + lq) * 132 + k0 + lr]);
            a[mt][1] = __float_as_uint(As[(rb + 8 + lq) * 132 + k0 + lr]);
            a[mt][2] = __float_as_uint(As[(rb + lq) * 132 + k0 + 4 + lr]);
            a[mt][3] = __float_as_uint(As[(rb + 8 + lq) * 132 + k0 + 4 + lr]);
        }
#pragma unroll
        for (int nt = 0; nt < 4; ++nt) {
            int nb = wn * 32 + nt * 8;
            b[nt][0] = __float_as_uint(Bs[(nb + lq) * 132 + k0 + lr]);
            b[nt][1] = __float_as_uint(Bs[(nb + lq) * 132 + k0 + 4 + lr]);
        }
#pragma unroll
        for (int mt = 0; mt < 2; ++mt)
#pragma unroll
            for (int nt = 0; nt < 4; ++nt)
                mma_tf32(acc[mt][nt], a[mt][0], a[mt][1], a[mt][2], a[mt][3],
                         b[nt][0], b[nt][1]);
    }
    __syncthreads();

    float* Cs = As;  // [128][68]
#pragma unroll
    for (int mt = 0; mt < 2; ++mt)
#pragma unroll
        for (int nt = 0; nt < 4; ++nt) {
            int row = wm * 32 + mt * 16 + lq;
            int col = wn * 32 + nt * 8 + 2 * lr;
            *(float2*)(Cs + row * 68 + col)       = make_float2(acc[mt][nt][0], acc[mt][nt][1]);
            *(float2*)(Cs + (row + 8) * 68 + col) = make_float2(acc[mt][nt][2], acc[mt][nt][3]);
        }
    __syncthreads();

#pragma unroll
    for (int it = 0; it < 8; ++it) {
        int idx = it * 256 + t;
        int j = idx >> 4, c4 = idx & 15;
        float4 v = *(float4*)(Cs + j * 68 + c4 * 4);
        float4 b = *(const float4*)(bout + n0 + c4 * 4);
        v.x += b.x; v.y += b.y; v.z += b.z; v.w += b.w;
        *(float4*)(out + (size_t)(p0 + j) * CC + n0 + c4 * 4) = v;
    }
}

// ---------------------------------------------------------------------------
extern "C" void kernel_launch(void* const* d_in, const int* in_sizes, int n_in,
                              void* d_out, int out_size)
{
    const float* x2d   = (const float*)d_in[0];
    const float* ln_g  = (const float*)d_in[1];
    const float* ln_b  = (const float*)d_in[2];
    const float* Wqkv  = (const float*)d_in[3];
    const float* Wbias = (const float*)d_in[4];
    const float* Wgate = (const float*)d_in[5];
    const float* bgate = (const float*)d_in[6];
    const float* Wout  = (const float*)d_in[7];
    const float* bout  = (const float*)d_in[8];
    float* out = (float*)d_out;

    const int smem_g = (128 * 132 + 64 * 132) * sizeof(float);  // 101376 B
    static bool attr_set = false;
    if (!attr_set) {
        cudaFuncSetAttribute(gemm512_kernel, cudaFuncAttributeMaxDynamicSharedMemorySize, smem_g);
        cudaFuncSetAttribute(gemm_out_kernel, cudaFuncAttributeMaxDynamicSharedMemorySize, smem_g);
        attr_set = true;
    }

    ln_kernel<<<NP / 8, 128>>>(x2d, ln_g, ln_b, Wbias);
    wprep_kernel<<<CC, 512>>>(Wqkv, Wgate);
    wprep2_kernel<<<CC, 128>>>(bgate, Wout);
    gemm512_kernel<<<dim3(512, 8), 256, smem_g>>>();
    phase2_kernel<<<dim3(2, NH, NN), 256>>>();
    gemm_out_kernel<<<dim3(512, 2), 256, smem_g>>>(bout, out);
}

// round 4
// speedup vs baseline: 2.7671x; 1.0131x over previous
#include <cuda_runtime.h>
#include <math.h>
#include <stdint.h>

#define NN 256
#define CC 128
#define CA 32
#define NH 4
#define NP (NN*NN)

static constexpr float LN_EPS_F = 1e-5f;
static constexpr float SCALE = 0.17677669529663689f;  // 1/sqrt(32)

// ---------------- scratch (device globals) ----------------
__device__ float g_lnx[(size_t)NP * CC];        // [p][c], tf32-rounded
__device__ float g_wbig[(size_t)CC * 512];      // [c][col], permuted, tf32-rounded
__device__ float g_bgate_p[128];                // permuted b_gate
__device__ float g_woutP[(size_t)CC * CC];      // [h*32+ca][out], tf32-rounded
__device__ float g_q[(size_t)NP * CA * NH];     // [i][h][j][ca]
__device__ float g_k[(size_t)NP * CA * NH];     // [i][h][k][ca]
__device__ float g_vT[(size_t)NP * CA * NH];    // [i][h][ca][k]
__device__ float g_gateP[(size_t)NP * CC];      // [p][h*32+ca]
__device__ float g_biasT[(size_t)NH * NP];      // [h][j][k]
__device__ float g_attg[(size_t)NP * CC];       // [p][h*32+ca]

__device__ __forceinline__ float to_tf32(float x) {
    uint32_t u;
    asm("cvt.rna.tf32.f32 %0, %1;" : "=r"(u) : "f"(x));
    return __uint_as_float(u);
}

__device__ __forceinline__ void mma_tf32(float* d, uint32_t a0, uint32_t a1,
                                         uint32_t a2, uint32_t a3,
                                         uint32_t b0, uint32_t b1) {
    asm volatile(
        "mma.sync.aligned.m16n8k8.row.col.f32.tf32.tf32.f32 "
        "{%0,%1,%2,%3}, {%4,%5,%6,%7}, {%8,%9}, {%0,%1,%2,%3};\n"
        : "+f"(d[0]), "+f"(d[1]), "+f"(d[2]), "+f"(d[3])
        : "r"(a0), "r"(a1), "r"(a2), "r"(a3), "r"(b0), "r"(b1));
}

__device__ __forceinline__ void ldm_x4(uint32_t* r, uint32_t saddr) {
    asm volatile("ldmatrix.sync.aligned.m8n8.x4.shared.b16 {%0,%1,%2,%3}, [%4];"
        : "=r"(r[0]), "=r"(r[1]), "=r"(r[2]), "=r"(r[3]) : "r"(saddr));
}

// ---------------------------------------------------------------------------
// LN + bias projection. 128 threads, 8 positions/block.
// ---------------------------------------------------------------------------
__global__ __launch_bounds__(128) void ln_kernel(
    const float* __restrict__ x, const float* __restrict__ ln_g, const float* __restrict__ ln_b,
    const float* __restrict__ Wbias)
{
    __shared__ float lnx[8][CC];
    __shared__ float redS[8][4], redS2[8][4];

    const int t = threadIdx.x;
    const int p0 = blockIdx.x * 8;
    const int lane = t & 31, warp = t >> 5;

    float xv[8];
#pragma unroll
    for (int p = 0; p < 8; ++p) xv[p] = x[(size_t)(p0 + p) * CC + t];

#pragma unroll
    for (int p = 0; p < 8; ++p) {
        float s = xv[p], s2 = xv[p] * xv[p];
#pragma unroll
        for (int o = 16; o > 0; o >>= 1) {
            s  += __shfl_xor_sync(0xffffffffu, s,  o);
            s2 += __shfl_xor_sync(0xffffffffu, s2, o);
        }
        if (lane == 0) { redS[p][warp] = s; redS2[p][warp] = s2; }
    }
    __syncthreads();

    const float gmul = ln_g[t], badd = ln_b[t];
#pragma unroll
    for (int p = 0; p < 8; ++p) {
        float s  = redS[p][0] + redS[p][1] + redS[p][2] + redS[p][3];
        float s2 = redS2[p][0] + redS2[p][1] + redS2[p][2] + redS2[p][3];
        float mu  = s * (1.0f / CC);
        float var = s2 * (1.0f / CC) - mu * mu;
        float v = (xv[p] - mu) * rsqrtf(var + LN_EPS_F) * gmul + badd;
        lnx[p][t] = v;
        g_lnx[(size_t)(p0 + p) * CC + t] = to_tf32(v);
    }
    __syncthreads();

    if (t < 32) {
        int h = t & 3, p = t >> 2;
        float acc = 0.0f;
#pragma unroll 4
        for (int c = 0; c < CC; ++c) acc += lnx[p][c] * Wbias[c * NH + h];
        int irow = p0 >> 8, j0 = p0 & 255;
        g_biasT[(size_t)h * NP + (size_t)(j0 + p) * NN + irow] = acc;
    }
}

// ---------------------------------------------------------------------------
// Weight prep.
// ---------------------------------------------------------------------------
__global__ __launch_bounds__(512) void wprep_kernel(
    const float* __restrict__ Wqkv, const float* __restrict__ Wgate)
{
    const int t = threadIdx.x, c = blockIdx.x;
    float v;
    if (t < 384) {
        int type = t / 128, r = t % 128, h = r / 32, ca = r % 32;
        v = Wqkv[c * 384 + ca * 12 + type * 4 + h];
    } else {
        int r = t - 384, h = r / 32, ca = r % 32;
        v = Wgate[c * 128 + ca * 4 + h];
    }
    g_wbig[c * 512 + t] = to_tf32(v);
}

__global__ __launch_bounds__(128) void wprep2_kernel(
    const float* __restrict__ bgate, const float* __restrict__ Wout)
{
    const int r = blockIdx.x;
    const int o = threadIdx.x;
    int h = r / 32, ca = r % 32;
    g_woutP[r * CC + o] = to_tf32(Wout[(ca * 4 + h) * CC + o]);
    if (o == 0) g_bgate_p[r] = bgate[ca * 4 + h];
}

// ---------------------------------------------------------------------------
// Shared mainloop: C[256x128] = A[256x128] @ B[128x128]^T-ish (Bs[n][k]).
// 8 warps, warp tile 64x64, ldmatrix fragments. acc[4][8][4] per warp.
// ---------------------------------------------------------------------------
#define LDA 132
struct FragAcc { float a[4][8][4]; };

__device__ __forceinline__ void mainloop_256x128(
    const float* As, const float* Bs, FragAcc& F, int lane, int wm, int wn)
{
#pragma unroll
    for (int mt = 0; mt < 4; ++mt)
#pragma unroll
        for (int nt = 0; nt < 8; ++nt)
#pragma unroll
            for (int e = 0; e < 4; ++e) F.a[mt][nt][e] = 0.0f;

    // ldmatrix address bases (bytes, shared space)
    const uint32_t As_s = (uint32_t)__cvta_generic_to_shared(As);
    const uint32_t Bs_s = (uint32_t)__cvta_generic_to_shared(Bs);
    const int arow = wm * 64 + (lane & 7) + ((lane & 8) ? 8 : 0);
    const int acol = (lane & 16) ? 4 : 0;
    const int brow = wn * 64 + (lane & 7) + ((lane & 16) ? 8 : 0);
    const int bcol = (lane & 8) ? 4 : 0;
    const uint32_t aBase = As_s + (uint32_t)(arow * LDA + acol) * 4u;
    const uint32_t bBase = Bs_s + (uint32_t)(brow * LDA + bcol) * 4u;

#pragma unroll 2
    for (int k0 = 0; k0 < 128; k0 += 8) {
        uint32_t a[4][4], b[4][4];
#pragma unroll
        for (int mt = 0; mt < 4; ++mt)
            ldm_x4(a[mt], aBase + (uint32_t)(mt * 16 * LDA + k0) * 4u);
#pragma unroll
        for (int np = 0; np < 4; ++np)
            ldm_x4(b[np], bBase + (uint32_t)(np * 16 * LDA + k0) * 4u);
#pragma unroll
        for (int mt = 0; mt < 4; ++mt)
#pragma unroll
            for (int nt = 0; nt < 8; ++nt)
                mma_tf32(F.a[mt][nt], a[mt][0], a[mt][1], a[mt][2], a[mt][3],
                         b[nt >> 1][(nt & 1) * 2], b[nt >> 1][(nt & 1) * 2 + 1]);
    }
}

__device__ __forceinline__ void store_acc_to_Cs(
    float* Cs, const FragAcc& F, int lane, int wm, int wn)
{
    const int lq = lane >> 2, lr = lane & 3;
#pragma unroll
    for (int mt = 0; mt < 4; ++mt)
#pragma unroll
        for (int nt = 0; nt < 8; ++nt) {
            int row = wm * 64 + mt * 16 + lq;
            int col = wn * 64 + nt * 8 + 2 * lr;
            *(float2*)(Cs + row * LDA + col)       = make_float2(F.a[mt][nt][0], F.a[mt][nt][1]);
            *(float2*)(Cs + (row + 8) * LDA + col) = make_float2(F.a[mt][nt][2], F.a[mt][nt][3]);
        }
}

// ---------------------------------------------------------------------------
// GEMM 65536x512x128: grid (256, 4). Block = one i-row (256 positions) x one
// output type (q / k / vT / gate).
// ---------------------------------------------------------------------------
__global__ __launch_bounds__(256, 1) void gemm512_kernel()
{
    extern __shared__ float sm[];
    float* As = sm;                 // [256][132]
    float* Bs = sm + 256 * LDA;     // [128][132]

    const int t = threadIdx.x;
    const int lane = t & 31, warp = t >> 5;
    const int wm = warp >> 1, wn = warp & 1;  // 4 x 2 warps, 64x64 each
    const int i = blockIdx.x;
    const int type = blockIdx.y;
    const int n0 = type * 128;
    const size_t p0 = (size_t)i * 256;

    // load A: 256x128 floats = 8192 float4
#pragma unroll
    for (int it = 0; it < 32; ++it) {
        int idx = it * 256 + t;
        int r = idx >> 5, c4 = idx & 31;
        float4 v = *(const float4*)(g_lnx + (p0 + r) * CC + c4 * 4);
        *(float4*)(As + r * LDA + c4 * 4) = v;
    }
    // load B transposed: Bs[n][k], 16384 floats
#pragma unroll
    for (int it = 0; it < 64; ++it) {
        int idx = it * 256 + t;
        int k = idx >> 7, n = idx & 127;
        Bs[n * LDA + k] = g_wbig[(size_t)k * 512 + n0 + n];
    }
    __syncthreads();

    FragAcc F;
    mainloop_256x128(As, Bs, F, lane, wm, wn);
    __syncthreads();

    float* Cs = As;  // reuse: [256][132]
    store_acc_to_Cs(Cs, F, lane, wm, wn);
    __syncthreads();

    if (type == 0 || type == 1) {
        float* dst0 = (type == 0) ? g_q : g_k;
#pragma unroll
        for (int h = 0; h < NH; ++h) {
            float* dst = dst0 + (size_t)(i * NH + h) * NN * CA;
#pragma unroll
            for (int it = 0; it < 8; ++it) {
                int idx = it * 256 + t;          // 2048 float4
                int j = idx >> 3, c4 = idx & 7;
                float4 v = *(float4*)(Cs + j * LDA + h * 32 + c4 * 4);
                *(float4*)(dst + j * CA + c4 * 4) = v;
            }
        }
    } else if (type == 2) {
        // vT[i][h][ca][j]
        for (int it = 0; it < 128; ++it) {
            int idx = it * 256 + t;              // 32768 floats
            int h = idx >> 13, ca = (idx >> 8) & 31, j = idx & 255;
            g_vT[((size_t)(i * NH + h) * CA + ca) * NN + j] = Cs[j * LDA + h * 32 + ca];
        }
    } else {
        // gate: sigmoid(C + bg), store [p][h*32+ca]
#pragma unroll
        for (int it = 0; it < 32; ++it) {
            int idx = it * 256 + t;              // 8192 float4
            int j = idx >> 5, c4 = idx & 31;
            float4 v = *(float4*)(Cs + j * LDA + c4 * 4);
            float4 bg = *(const float4*)(g_bgate_p + c4 * 4);
            v.x = 1.0f / (1.0f + __expf(-(v.x + bg.x)));
            v.y = 1.0f / (1.0f + __expf(-(v.y + bg.y)));
            v.z = 1.0f / (1.0f + __expf(-(v.z + bg.z)));
            v.w = 1.0f / (1.0f + __expf(-(v.w + bg.w)));
            *(float4*)(g_gateP + (p0 + j) * CC + c4 * 4) = v;
        }
    }
}

// ---------------------------------------------------------------------------
// Phase 2: register-resident flash attention (unchanged from R3).
// ---------------------------------------------------------------------------
__global__ __launch_bounds__(256, 2) void phase2_kernel()
{
    __shared__ float Ks[64 * 36];
    __shared__ float Vts[32 * 68];

    const int jt = blockIdx.x, h = blockIdx.y, i = blockIdx.z;
    const int t = threadIdx.x, lane = t & 31, warp = t >> 5;
    const int lq = lane >> 2, lr = lane & 3;
    const size_t base = (size_t)(i * NH + h) * NN * CA;
    const int rb = jt * 128 + warp * 16;

    uint32_t qa[4][4];
    {
        const float* Qp = g_q + base;
#pragma unroll
        for (int kk = 0; kk < 4; ++kk) {
            int k0 = kk * 8;
            qa[kk][0] = __float_as_uint(to_tf32(Qp[(rb + lq) * CA + k0 + lr] * SCALE));
            qa[kk][1] = __float_as_uint(to_tf32(Qp[(rb + 8 + lq) * CA + k0 + lr] * SCALE));
            qa[kk][2] = __float_as_uint(to_tf32(Qp[(rb + lq) * CA + k0 + 4 + lr] * SCALE));
            qa[kk][3] = __float_as_uint(to_tf32(Qp[(rb + 8 + lq) * CA + k0 + 4 + lr] * SCALE));
        }
    }

    float o[4][4];
#pragma unroll
    for (int nt = 0; nt < 4; ++nt)
#pragma unroll
        for (int e = 0; e < 4; ++e) o[nt][e] = 0.0f;
    float m0 = -1e30f, m1 = -1e30f, l0 = 0.0f, l1 = 0.0f;

    const float* biasRow0 = g_biasT + (size_t)h * NP + (size_t)(rb + lq) * NN;
    const float* biasRow1 = biasRow0 + 8 * NN;

    for (int kt = 0; kt < 4; ++kt) {
#pragma unroll
        for (int it = 0; it < 2; ++it) {
            int id = it * 256 + t;
            int r = id >> 3, c4 = id & 7;
            float4 v = *(const float4*)(g_k + base + (size_t)(kt * 64 + r) * CA + c4 * 4);
            v.x = to_tf32(v.x); v.y = to_tf32(v.y); v.z = to_tf32(v.z); v.w = to_tf32(v.w);
            *(float4*)(Ks + r * 36 + c4 * 4) = v;
        }
#pragma unroll
        for (int it = 0; it < 2; ++it) {
            int id = it * 256 + t;
            int ca = id >> 4, c4 = id & 15;
            float4 v = *(const float4*)(g_vT + base + (size_t)ca * NN + kt * 64 + c4 * 4);
            v.x = to_tf32(v.x); v.y = to_tf32(v.y); v.z = to_tf32(v.z); v.w = to_tf32(v.w);
            *(float4*)(Vts + ca * 68 + c4 * 4) = v;
        }
        __syncthreads();

        float s[8][4];
#pragma unroll
        for (int nt = 0; nt < 8; ++nt)
#pragma unroll
            for (int e = 0; e < 4; ++e) s[nt][e] = 0.0f;

#pragma unroll
        for (int kk = 0; kk < 4; ++kk) {
            int k0 = kk * 8;
#pragma unroll
            for (int nt = 0; nt < 8; ++nt) {
                uint32_t b0 = __float_as_uint(Ks[(nt * 8 + lq) * 36 + k0 + lr]);
                uint32_t b1 = __float_as_uint(Ks[(nt * 8 + lq) * 36 + k0 + 4 + lr]);
                mma_tf32(s[nt], qa[kk][0], qa[kk][1], qa[kk][2], qa[kk][3], b0, b1);
            }
        }

#pragma unroll
        for (int nt = 0; nt < 8; ++nt) {
            int kc = kt * 64 + nt * 8 + 2 * lr;
            float2 bA = *(const float2*)(biasRow0 + kc);
            float2 bB = *(const float2*)(biasRow1 + kc);
            s[nt][0] += bA.x; s[nt][1] += bA.y;
            s[nt][2] += bB.x; s[nt][3] += bB.y;
        }

        float tm0 = -1e30f, tm1 = -1e30f;
#pragma unroll
        for (int nt = 0; nt < 8; ++nt) {
            tm0 = fmaxf(tm0, fmaxf(s[nt][0], s[nt][1]));
            tm1 = fmaxf(tm1, fmaxf(s[nt][2], s[nt][3]));
        }
        tm0 = fmaxf(tm0, __shfl_xor_sync(0xffffffffu, tm0, 1));
        tm0 = fmaxf(tm0, __shfl_xor_sync(0xffffffffu, tm0, 2));
        tm1 = fmaxf(tm1, __shfl_xor_sync(0xffffffffu, tm1, 1));
        tm1 = fmaxf(tm1, __shfl_xor_sync(0xffffffffu, tm1, 2));

        float nm0 = fmaxf(m0, tm0), nm1 = fmaxf(m1, tm1);
        float c0 = __expf(m0 - nm0), c1 = __expf(m1 - nm1);
        m0 = nm0; m1 = nm1;
        l0 *= c0; l1 *= c1;
#pragma unroll
        for (int nt = 0; nt < 4; ++nt) {
            o[nt][0] *= c0; o[nt][1] *= c0;
            o[nt][2] *= c1; o[nt][3] *= c1;
        }

        float ps0 = 0.0f, ps1 = 0.0f;
#pragma unroll
        for (int nt = 0; nt < 8; ++nt) {
            s[nt][0] = __expf(s[nt][0] - m0);
            s[nt][1] = __expf(s[nt][1] - m0);
            s[nt][2] = __expf(s[nt][2] - m1);
            s[nt][3] = __expf(s[nt][3] - m1);
            ps0 += s[nt][0] + s[nt][1];
            ps1 += s[nt][2] + s[nt][3];
        }
        ps0 += __shfl_xor_sync(0xffffffffu, ps0, 1);
        ps0 += __shfl_xor_sync(0xffffffffu, ps0, 2);
        ps1 += __shfl_xor_sync(0xffffffffu, ps1, 1);
        ps1 += __shfl_xor_sync(0xffffffffu, ps1, 2);
        l0 += ps0; l1 += ps1;

        const int src0 = (lane & ~3) | (lr >> 1);
        const int src2 = src0 + 2;
        const bool odd = lr & 1;
#pragma unroll
        for (int ks = 0; ks < 8; ++ks) {
            float t00 = __shfl_sync(0xffffffffu, s[ks][0], src0);
            float t01 = __shfl_sync(0xffffffffu, s[ks][1], src0);
            float t10 = __shfl_sync(0xffffffffu, s[ks][2], src0);
            float t11 = __shfl_sync(0xffffffffu, s[ks][3], src0);
            float u00 = __shfl_sync(0xffffffffu, s[ks][0], src2);
            float u01 = __shfl_sync(0xffffffffu, s[ks][1], src2);
            float u10 = __shfl_sync(0xffffffffu, s[ks][2], src2);
            float u11 = __shfl_sync(0xffffffffu, s[ks][3], src2);
            uint32_t a0 = __float_as_uint(odd ? t01 : t00);
            uint32_t a1 = __float_as_uint(odd ? t11 : t10);
            uint32_t a2 = __float_as_uint(odd ? u01 : u00);
            uint32_t a3 = __float_as_uint(odd ? u11 : u10);
#pragma unroll
            for (int nt = 0; nt < 4; ++nt) {
                uint32_t b0 = __float_as_uint(Vts[(nt * 8 + lq) * 68 + ks * 8 + lr]);
                uint32_t b1 = __float_as_uint(Vts[(nt * 8 + lq) * 68 + ks * 8 + 4 + lr]);
                mma_tf32(o[nt], a0, a1, a2, a3, b0, b1);
            }
        }
        __syncthreads();
    }

    const float inv0 = 1.0f / l0, inv1 = 1.0f / l1;
    const size_t p0r = (size_t)i * NN + rb + lq;
    const size_t p1r = p0r + 8;
#pragma unroll
    for (int nt = 0; nt < 4; ++nt) {
        int col = h * 32 + nt * 8 + 2 * lr;
        float2 g0 = *(const float2*)(g_gateP + p0r * CC + col);
        float2 g1 = *(const float2*)(g_gateP + p1r * CC + col);
        *(float2*)(g_attg + p0r * CC + col) =
            make_float2(o[nt][0] * inv0 * g0.x, o[nt][1] * inv0 * g0.y);
        *(float2*)(g_attg + p1r * CC + col) =
            make_float2(o[nt][2] * inv1 * g1.x, o[nt][3] * inv1 * g1.y);
    }
}

// ---------------------------------------------------------------------------
// GEMM 65536x128x128: out = attg @ woutP + b_out. Grid (256, 1), CTA 256x128.
// ---------------------------------------------------------------------------
__global__ __launch_bounds__(256, 1) void gemm_out_kernel(
    const float* __restrict__ bout, float* __restrict__ out)
{
    extern __shared__ float sm[];
    float* As = sm;                 // [256][132]
    float* Bs = sm + 256 * LDA;     // [128][132]

    const int t = threadIdx.x;
    const int lane = t & 31, warp = t >> 5;
    const int wm = warp >> 1, wn = warp & 1;
    const size_t p0 = (size_t)blockIdx.x * 256;

#pragma unroll
    for (int it = 0; it < 32; ++it) {
        int idx = it * 256 + t;
        int r = idx >> 5, c4 = idx & 31;
        float4 v = *(const float4*)(g_attg + (p0 + r) * CC + c4 * 4);
        *(float4*)(As + r * LDA + c4 * 4) = v;
    }
#pragma unroll
    for (int it = 0; it < 64; ++it) {
        int idx = it * 256 + t;
        int k = idx >> 7, n = idx & 127;
        Bs[n * LDA + k] = g_woutP[(size_t)k * CC + n];
    }
    __syncthreads();

    FragAcc F;
    mainloop_256x128(As, Bs, F, lane, wm, wn);
    __syncthreads();

    float* Cs = As;
    store_acc_to_Cs(Cs, F, lane, wm, wn);
    __syncthreads();

#pragma unroll
    for (int it = 0; it < 32; ++it) {
        int idx = it * 256 + t;                 // 8192 float4
        int j = idx >> 5, c4 = idx & 31;
        float4 v = *(float4*)(Cs + j * LDA + c4 * 4);
        float4 b = *(const float4*)(bout + c4 * 4);
        v.x += b.x; v.y += b.y; v.z += b.z; v.w += b.w;
        *(float4*)(out + (p0 + j) * CC + c4 * 4) = v;
    }
}

// ---------------------------------------------------------------------------
extern "C" void kernel_launch(void* const* d_in, const int* in_sizes, int n_in,
                              void* d_out, int out_size)
{
    const float* x2d   = (const float*)d_in[0];
    const float* ln_g  = (const float*)d_in[1];
    const float* ln_b  = (const float*)d_in[2];
    const float* Wqkv  = (const float*)d_in[3];
    const float* Wbias = (const float*)d_in[4];
    const float* Wgate = (const float*)d_in[5];
    const float* bgate = (const float*)d_in[6];
    const float* Wout  = (const float*)d_in[7];
    const float* bout  = (const float*)d_in[8];
    float* out = (float*)d_out;

    const int smem_g = (256 * LDA + 128 * LDA) * sizeof(float);  // 202752 B
    static bool attr_set = false;
    if (!attr_set) {
        cudaFuncSetAttribute(gemm512_kernel, cudaFuncAttributeMaxDynamicSharedMemorySize, smem_g);
        cudaFuncSetAttribute(gemm_out_kernel, cudaFuncAttributeMaxDynamicSharedMemorySize, smem_g);
        attr_set = true;
    }

    ln_kernel<<<NP / 8, 128>>>(x2d, ln_g, ln_b, Wbias);
    wprep_kernel<<<CC, 512>>>(Wqkv, Wgate);
    wprep2_kernel<<<CC, 128>>>(bgate, Wout);
    gemm512_kernel<<<dim3(256, 4), 256, smem_g>>>();
    phase2_kernel<<<dim3(2, NH, NN), 256>>>();
    gemm_out_kernel<<<dim3(256, 1), 256, smem_g>>>(bout, out);
}

// round 5
// speedup vs baseline: 3.0903x; 1.1168x over previous
#include <cuda_runtime.h>
#include <math.h>
#include <stdint.h>

#define NN 256
#define CC 128
#define CA 32
#define NH 4
#define NP (NN*NN)

static constexpr float LN_EPS_F = 1e-5f;
static constexpr float SCALE = 0.17677669529663689f;  // 1/sqrt(32)

// ---------------- scratch (device globals) ----------------
__device__ float g_lnx[(size_t)NP * CC];        // [p][c], tf32-rounded
__device__ float g_wbigT[(size_t)512 * CC];     // [col][k], permuted, tf32-rounded
__device__ float g_bgate_p[128];                // permuted b_gate
__device__ float g_woutT[(size_t)CC * CC];      // [out][k=h*32+ca], tf32-rounded
__device__ float g_q[(size_t)NP * CA * NH];     // [i][h][j][ca]
__device__ float g_k[(size_t)NP * CA * NH];     // [i][h][k][ca]
__device__ float g_vT[(size_t)NP * CA * NH];    // [i][h][ca][k]
__device__ float g_gateP[(size_t)NP * CC];      // [p][h*32+ca]
__device__ float g_biasT[(size_t)NH * NP];      // [h][j][k]
__device__ float g_attg[(size_t)NP * CC];       // [p][h*32+ca]

__device__ __forceinline__ float to_tf32(float x) {
    uint32_t u;
    asm("cvt.rna.tf32.f32 %0, %1;" : "=r"(u) : "f"(x));
    return __uint_as_float(u);
}

__device__ __forceinline__ void mma_tf32(float* d, uint32_t a0, uint32_t a1,
                                         uint32_t a2, uint32_t a3,
                                         uint32_t b0, uint32_t b1) {
    asm volatile(
        "mma.sync.aligned.m16n8k8.row.col.f32.tf32.tf32.f32 "
        "{%0,%1,%2,%3}, {%4,%5,%6,%7}, {%8,%9}, {%0,%1,%2,%3};\n"
        : "+f"(d[0]), "+f"(d[1]), "+f"(d[2]), "+f"(d[3])
        : "r"(a0), "r"(a1), "r"(a2), "r"(a3), "r"(b0), "r"(b1));
}

__device__ __forceinline__ void ldm_x4(uint32_t* r, uint32_t saddr) {
    asm volatile("ldmatrix.sync.aligned.m8n8.x4.shared.b16 {%0,%1,%2,%3}, [%4];"
        : "=r"(r[0]), "=r"(r[1]), "=r"(r[2]), "=r"(r[3]) : "r"(saddr));
}

__device__ __forceinline__ void cp_async16(uint32_t d, const void* s) {
    asm volatile("cp.async.cg.shared.global [%0], [%1], 16;" :: "r"(d), "l"(s));
}
__device__ __forceinline__ void cp_commit() {
    asm volatile("cp.async.commit_group;");
}
template <int N>
__device__ __forceinline__ void cp_wait() {
    asm volatile("cp.async.wait_group %0;" :: "n"(N));
}

// ---------------------------------------------------------------------------
// LN + bias projection. 128 threads, 8 positions/block.
// ---------------------------------------------------------------------------
__global__ __launch_bounds__(128) void ln_kernel(
    const float* __restrict__ x, const float* __restrict__ ln_g, const float* __restrict__ ln_b,
    const float* __restrict__ Wbias)
{
    __shared__ float lnx[8][CC];
    __shared__ float redS[8][4], redS2[8][4];

    const int t = threadIdx.x;
    const int p0 = blockIdx.x * 8;
    const int lane = t & 31, warp = t >> 5;

    float xv[8];
#pragma unroll
    for (int p = 0; p < 8; ++p) xv[p] = x[(size_t)(p0 + p) * CC + t];

#pragma unroll
    for (int p = 0; p < 8; ++p) {
        float s = xv[p], s2 = xv[p] * xv[p];
#pragma unroll
        for (int o = 16; o > 0; o >>= 1) {
            s  += __shfl_xor_sync(0xffffffffu, s,  o);
            s2 += __shfl_xor_sync(0xffffffffu, s2, o);
        }
        if (lane == 0) { redS[p][warp] = s; redS2[p][warp] = s2; }
    }
    __syncthreads();

    const float gmul = ln_g[t], badd = ln_b[t];
#pragma unroll
    for (int p = 0; p < 8; ++p) {
        float s  = redS[p][0] + redS[p][1] + redS[p][2] + redS[p][3];
        float s2 = redS2[p][0] + redS2[p][1] + redS2[p][2] + redS2[p][3];
        float mu  = s * (1.0f / CC);
        float var = s2 * (1.0f / CC) - mu * mu;
        float v = (xv[p] - mu) * rsqrtf(var + LN_EPS_F) * gmul + badd;
        lnx[p][t] = v;
        g_lnx[(size_t)(p0 + p) * CC + t] = to_tf32(v);
    }
    __syncthreads();

    if (t < 32) {
        int h = t & 3, p = t >> 2;
        float acc = 0.0f;
#pragma unroll 4
        for (int c = 0; c < CC; ++c) acc += lnx[p][c] * Wbias[c * NH + h];
        int irow = p0 >> 8, j0 = p0 & 255;
        g_biasT[(size_t)h * NP + (size_t)(j0 + p) * NN + irow] = acc;
    }
}

// ---------------------------------------------------------------------------
// Weight prep: write TRANSPOSED permuted weights [col][k].
// ---------------------------------------------------------------------------
__global__ __launch_bounds__(512) void wprep_kernel(
    const float* __restrict__ Wqkv, const float* __restrict__ Wgate)
{
    const int t = threadIdx.x, c = blockIdx.x;
    float v;
    if (t < 384) {
        int type = t / 128, r = t % 128, h = r / 32, ca = r % 32;
        v = Wqkv[c * 384 + ca * 12 + type * 4 + h];
    } else {
        int r = t - 384, h = r / 32, ca = r % 32;
        v = Wgate[c * 128 + ca * 4 + h];
    }
    g_wbigT[(size_t)t * CC + c] = to_tf32(v);
}

__global__ __launch_bounds__(128) void wprep2_kernel(
    const float* __restrict__ bgate, const float* __restrict__ Wout)
{
    const int r = blockIdx.x;         // k index: h*32+ca
    const int o = threadIdx.x;        // output channel
    int h = r / 32, ca = r % 32;
    g_woutT[(size_t)o * CC + r] = to_tf32(Wout[(ca * 4 + h) * CC + o]);
    if (o == 0) g_bgate_p[r] = bgate[ca * 4 + h];
}

// ---------------------------------------------------------------------------
// Pipelined 128x128x128 CTA GEMM core. 8 warps (4x2), warp tile 32x64.
// K chunked at 32, cp.async double-buffered. Row stride 36 (conflict-free).
// ---------------------------------------------------------------------------
#define CHK 32
#define LDS_S 36
#define ABUF(b) ((b) * 128 * LDS_S)
#define BBUF(b) (2 * 128 * LDS_S + (b) * 128 * LDS_S)
#define GEMM_SMEM_BYTES (4 * 128 * LDS_S * 4)   // 73728
#define LDC 132

__device__ __forceinline__ void load_chunk(
    float* sm, uint32_t smemBase, int buf, const float* gA, const float* gB,
    int ck, int t)
{
    const uint32_t aAddr = smemBase + ABUF(buf) * 4u;
    const uint32_t bAddr = smemBase + BBUF(buf) * 4u;
#pragma unroll
    for (int q = 0; q < 4; ++q) {
        int idx = q * 256 + t;            // 1024 x 16B = A chunk 128x32
        int r = idx >> 3, c4 = idx & 7;
        cp_async16(aAddr + (uint32_t)(r * LDS_S + c4 * 4) * 4u,
                   gA + (size_t)r * CC + ck * CHK + c4 * 4);
    }
#pragma unroll
    for (int q = 0; q < 4; ++q) {
        int idx = q * 256 + t;
        int n = idx >> 3, c4 = idx & 7;
        cp_async16(bAddr + (uint32_t)(n * LDS_S + c4 * 4) * 4u,
                   gB + (size_t)n * CC + ck * CHK + c4 * 4);
    }
}

__device__ __forceinline__ void compute_chunk(
    uint32_t smemBase, int buf, float (&acc)[2][8][4], int lane, int wm, int wn)
{
    const int arow = wm * 32 + (lane & 7) + ((lane & 8) ? 8 : 0);
    const int acol = (lane & 16) ? 4 : 0;
    const int brow = wn * 64 + (lane & 7) + ((lane & 16) ? 8 : 0);
    const int bcol = (lane & 8) ? 4 : 0;
    const uint32_t aBase = smemBase + (ABUF(buf) + arow * LDS_S + acol) * 4u;
    const uint32_t bBase = smemBase + (BBUF(buf) + brow * LDS_S + bcol) * 4u;

#pragma unroll
    for (int k0 = 0; k0 < CHK; k0 += 8) {
        uint32_t a[2][4], b[4][4];
#pragma unroll
        for (int mt = 0; mt < 2; ++mt)
            ldm_x4(a[mt], aBase + (uint32_t)(mt * 16 * LDS_S + k0) * 4u);
#pragma unroll
        for (int np = 0; np < 4; ++np)
            ldm_x4(b[np], bBase + (uint32_t)(np * 16 * LDS_S + k0) * 4u);
#pragma unroll
        for (int mt = 0; mt < 2; ++mt)
#pragma unroll
            for (int nt = 0; nt < 8; ++nt)
                mma_tf32(acc[mt][nt], a[mt][0], a[mt][1], a[mt][2], a[mt][3],
                         b[nt >> 1][(nt & 1) * 2], b[nt >> 1][(nt & 1) * 2 + 1]);
    }
}

__device__ __forceinline__ void gemm_pipeline(
    float* sm, const float* gA, const float* gB, float (&acc)[2][8][4],
    int t, int lane, int wm, int wn)
{
#pragma unroll
    for (int mt = 0; mt < 2; ++mt)
#pragma unroll
        for (int nt = 0; nt < 8; ++nt)
#pragma unroll
            for (int e = 0; e < 4; ++e) acc[mt][nt][e] = 0.0f;

    const uint32_t smemBase = (uint32_t)__cvta_generic_to_shared(sm);
    load_chunk(sm, smemBase, 0, gA, gB, 0, t);
    cp_commit();
#pragma unroll
    for (int ck = 0; ck < 4; ++ck) {
        if (ck + 1 < 4) {
            load_chunk(sm, smemBase, (ck + 1) & 1, gA, gB, ck + 1, t);
            cp_commit();
            cp_wait<1>();
        } else {
            cp_wait<0>();
        }
        __syncthreads();
        compute_chunk(smemBase, ck & 1, acc, lane, wm, wn);
        __syncthreads();
    }
}

__device__ __forceinline__ void store_acc_to_Cs(
    float* Cs, const float (&acc)[2][8][4], int lane, int wm, int wn)
{
    const int lq = lane >> 2, lr = lane & 3;
#pragma unroll
    for (int mt = 0; mt < 2; ++mt)
#pragma unroll
        for (int nt = 0; nt < 8; ++nt) {
            int row = wm * 32 + mt * 16 + lq;
            int col = wn * 64 + nt * 8 + 2 * lr;
            *(float2*)(Cs + row * LDC + col)       = make_float2(acc[mt][nt][0], acc[mt][nt][1]);
            *(float2*)(Cs + (row + 8) * LDC + col) = make_float2(acc[mt][nt][2], acc[mt][nt][3]);
        }
}

// ---------------------------------------------------------------------------
// GEMM 65536x512x128: grid (512, 4). Block = 128 positions x one type.
// ---------------------------------------------------------------------------
__global__ __launch_bounds__(256, 2) void gemm512_kernel()
{
    extern __shared__ float sm[];
    const int t = threadIdx.x;
    const int lane = t & 31, warp = t >> 5;
    const int wm = warp >> 1, wn = warp & 1;
    const int type = blockIdx.y;
    const size_t p0 = (size_t)blockIdx.x * 128;
    const float* gA = g_lnx + p0 * CC;
    const float* gB = g_wbigT + (size_t)type * 128 * CC;

    float acc[2][8][4];
    gemm_pipeline(sm, gA, gB, acc, t, lane, wm, wn);

    float* Cs = sm;  // [128][132] = 67.6KB fits in the 73.7KB buffers
    store_acc_to_Cs(Cs, acc, lane, wm, wn);
    __syncthreads();

    const int i = (int)(p0 >> 8);
    const int j0 = (int)(p0 & 255);

    if (type == 0 || type == 1) {
        float* dst0 = (type == 0) ? g_q : g_k;
#pragma unroll
        for (int h = 0; h < NH; ++h) {
            float* dst = dst0 + ((size_t)(i * NH + h) * NN + j0) * CA;
#pragma unroll
            for (int it = 0; it < 4; ++it) {
                int idx = it * 256 + t;          // 1024 float4
                int j = idx >> 3, c4 = idx & 7;
                float4 v = *(float4*)(Cs + j * LDC + h * 32 + c4 * 4);
                *(float4*)(dst + j * CA + c4 * 4) = v;
            }
        }
    } else if (type == 2) {
#pragma unroll
        for (int it = 0; it < 64; ++it) {
            int idx = it * 256 + t;              // 16384 floats
            int h = idx >> 12, ca = (idx >> 7) & 31, j = idx & 127;
            g_vT[((size_t)(i * NH + h) * CA + ca) * NN + j0 + j] = Cs[j * LDC + h * 32 + ca];
        }
    } else {
#pragma unroll
        for (int it = 0; it < 16; ++it) {
            int idx = it * 256 + t;              // 4096 float4
            int j = idx >> 5, c4 = idx & 31;
            float4 v = *(float4*)(Cs + j * LDC + c4 * 4);
            float4 bg = *(const float4*)(g_bgate_p + c4 * 4);
            v.x = 1.0f / (1.0f + __expf(-(v.x + bg.x)));
            v.y = 1.0f / (1.0f + __expf(-(v.y + bg.y)));
            v.z = 1.0f / (1.0f + __expf(-(v.z + bg.z)));
            v.w = 1.0f / (1.0f + __expf(-(v.w + bg.w)));
            *(float4*)(g_gateP + (p0 + j) * CC + c4 * 4) = v;
        }
    }
}

// ---------------------------------------------------------------------------
// Phase 2: register-resident flash attention (unchanged).
// ---------------------------------------------------------------------------
__global__ __launch_bounds__(256, 2) void phase2_kernel()
{
    __shared__ float Ks[64 * 36];
    __shared__ float Vts[32 * 68];

    const int jt = blockIdx.x, h = blockIdx.y, i = blockIdx.z;
    const int t = threadIdx.x, lane = t & 31, warp = t >> 5;
    const int lq = lane >> 2, lr = lane & 3;
    const size_t base = (size_t)(i * NH + h) * NN * CA;
    const int rb = jt * 128 + warp * 16;

    uint32_t qa[4][4];
    {
        const float* Qp = g_q + base;
#pragma unroll
        for (int kk = 0; kk < 4; ++kk) {
            int k0 = kk * 8;
            qa[kk][0] = __float_as_uint(to_tf32(Qp[(rb + lq) * CA + k0 + lr] * SCALE));
            qa[kk][1] = __float_as_uint(to_tf32(Qp[(rb + 8 + lq) * CA + k0 + lr] * SCALE));
            qa[kk][2] = __float_as_uint(to_tf32(Qp[(rb + lq) * CA + k0 + 4 + lr] * SCALE));
            qa[kk][3] = __float_as_uint(to_tf32(Qp[(rb + 8 + lq) * CA + k0 + 4 + lr] * SCALE));
        }
    }

    float o[4][4];
#pragma unroll
    for (int nt = 0; nt < 4; ++nt)
#pragma unroll
        for (int e = 0; e < 4; ++e) o[nt][e] = 0.0f;
    float m0 = -1e30f, m1 = -1e30f, l0 = 0.0f, l1 = 0.0f;

    const float* biasRow0 = g_biasT + (size_t)h * NP + (size_t)(rb + lq) * NN;
    const float* biasRow1 = biasRow0 + 8 * NN;

    for (int kt = 0; kt < 4; ++kt) {
#pragma unroll
        for (int it = 0; it < 2; ++it) {
            int id = it * 256 + t;
            int r = id >> 3, c4 = id & 7;
            float4 v = *(const float4*)(g_k + base + (size_t)(kt * 64 + r) * CA + c4 * 4);
            v.x = to_tf32(v.x); v.y = to_tf32(v.y); v.z = to_tf32(v.z); v.w = to_tf32(v.w);
            *(float4*)(Ks + r * 36 + c4 * 4) = v;
        }
#pragma unroll
        for (int it = 0; it < 2; ++it) {
            int id = it * 256 + t;
            int ca = id >> 4, c4 = id & 15;
            float4 v = *(const float4*)(g_vT + base + (size_t)ca * NN + kt * 64 + c4 * 4);
            v.x = to_tf32(v.x); v.y = to_tf32(v.y); v.z = to_tf32(v.z); v.w = to_tf32(v.w);
            *(float4*)(Vts + ca * 68 + c4 * 4) = v;
        }
        __syncthreads();

        float s[8][4];
#pragma unroll
        for (int nt = 0; nt < 8; ++nt)
#pragma unroll
            for (int e = 0; e < 4; ++e) s[nt][e] = 0.0f;

#pragma unroll
        for (int kk = 0; kk < 4; ++kk) {
            int k0 = kk * 8;
#pragma unroll
            for (int nt = 0; nt < 8; ++nt) {
                uint32_t b0 = __float_as_uint(Ks[(nt * 8 + lq) * 36 + k0 + lr]);
                uint32_t b1 = __float_as_uint(Ks[(nt * 8 + lq) * 36 + k0 + 4 + lr]);
                mma_tf32(s[nt], qa[kk][0], qa[kk][1], qa[kk][2], qa[kk][3], b0, b1);
            }
        }

#pragma unroll
        for (int nt = 0; nt < 8; ++nt) {
            int kc = kt * 64 + nt * 8 + 2 * lr;
            float2 bA = *(const float2*)(biasRow0 + kc);
            float2 bB = *(const float2*)(biasRow1 + kc);
            s[nt][0] += bA.x; s[nt][1] += bA.y;
            s[nt][2] += bB.x; s[nt][3] += bB.y;
        }

        float tm0 = -1e30f, tm1 = -1e30f;
#pragma unroll
        for (int nt = 0; nt < 8; ++nt) {
            tm0 = fmaxf(tm0, fmaxf(s[nt][0], s[nt][1]));
            tm1 = fmaxf(tm1, fmaxf(s[nt][2], s[nt][3]));
        }
        tm0 = fmaxf(tm0, __shfl_xor_sync(0xffffffffu, tm0, 1));
        tm0 = fmaxf(tm0, __shfl_xor_sync(0xffffffffu, tm0, 2));
        tm1 = fmaxf(tm1, __shfl_xor_sync(0xffffffffu, tm1, 1));
        tm1 = fmaxf(tm1, __shfl_xor_sync(0xffffffffu, tm1, 2));

        float nm0 = fmaxf(m0, tm0), nm1 = fmaxf(m1, tm1);
        float c0 = __expf(m0 - nm0), c1 = __expf(m1 - nm1);
        m0 = nm0; m1 = nm1;
        l0 *= c0; l1 *= c1;
#pragma unroll
        for (int nt = 0; nt < 4; ++nt) {
            o[nt][0] *= c0; o[nt][1] *= c0;
            o[nt][2] *= c1; o[nt][3] *= c1;
        }

        float ps0 = 0.0f, ps1 = 0.0f;
#pragma unroll
        for (int nt = 0; nt < 8; ++nt) {
            s[nt][0] = __expf(s[nt][0] - m0);
            s[nt][1] = __expf(s[nt][1] - m0);
            s[nt][2] = __expf(s[nt][2] - m1);
            s[nt][3] = __expf(s[nt][3] - m1);
            ps0 += s[nt][0] + s[nt][1];
            ps1 += s[nt][2] + s[nt][3];
        }
        ps0 += __shfl_xor_sync(0xffffffffu, ps0, 1);
        ps0 += __shfl_xor_sync(0xffffffffu, ps0, 2);
        ps1 += __shfl_xor_sync(0xffffffffu, ps1, 1);
        ps1 += __shfl_xor_sync(0xffffffffu, ps1, 2);
        l0 += ps0; l1 += ps1;

        const int src0 = (lane & ~3) | (lr >> 1);
        const int src2 = src0 + 2;
        const bool odd = lr & 1;
#pragma unroll
        for (int ks = 0; ks < 8; ++ks) {
            float t00 = __shfl_sync(0xffffffffu, s[ks][0], src0);
            float t01 = __shfl_sync(0xffffffffu, s[ks][1], src0);
            float t10 = __shfl_sync(0xffffffffu, s[ks][2], src0);
            float t11 = __shfl_sync(0xffffffffu, s[ks][3], src0);
            float u00 = __shfl_sync(0xffffffffu, s[ks][0], src2);
            float u01 = __shfl_sync(0xffffffffu, s[ks][1], src2);
            float u10 = __shfl_sync(0xffffffffu, s[ks][2], src2);
            float u11 = __shfl_sync(0xffffffffu, s[ks][3], src2);
            uint32_t a0 = __float_as_uint(odd ? t01 : t00);
            uint32_t a1 = __float_as_uint(odd ? t11 : t10);
            uint32_t a2 = __float_as_uint(odd ? u01 : u00);
            uint32_t a3 = __float_as_uint(odd ? u11 : u10);
#pragma unroll
            for (int nt = 0; nt < 4; ++nt) {
                uint32_t b0 = __float_as_uint(Vts[(nt * 8 + lq) * 68 + ks * 8 + lr]);
                uint32_t b1 = __float_as_uint(Vts[(nt * 8 + lq) * 68 + ks * 8 + 4 + lr]);
                mma_tf32(o[nt], a0, a1, a2, a3, b0, b1);
            }
        }
        __syncthreads();
    }

    const float inv0 = 1.0f / l0, inv1 = 1.0f / l1;
    const size_t p0r = (size_t)i * NN + rb + lq;
    const size_t p1r = p0r + 8;
#pragma unroll
    for (int nt = 0; nt < 4; ++nt) {
        int col = h * 32 + nt * 8 + 2 * lr;
        float2 g0 = *(const float2*)(g_gateP + p0r * CC + col);
        float2 g1 = *(const float2*)(g_gateP + p1r * CC + col);
        *(float2*)(g_attg + p0r * CC + col) =
            make_float2(o[nt][0] * inv0 * g0.x, o[nt][1] * inv0 * g0.y);
        *(float2*)(g_attg + p1r * CC + col) =
            make_float2(o[nt][2] * inv1 * g1.x, o[nt][3] * inv1 * g1.y);
    }
}

// ---------------------------------------------------------------------------
// GEMM 65536x128x128: out = attg @ Wout^T(permuted) + b_out. Grid (512).
// ---------------------------------------------------------------------------
__global__ __launch_bounds__(256, 2) void gemm_out_kernel(
    const float* __restrict__ bout, float* __restrict__ out)
{
    extern __shared__ float sm[];
    const int t = threadIdx.x;
    const int lane = t & 31, warp = t >> 5;
    const int wm = warp >> 1, wn = warp & 1;
    const size_t p0 = (size_t)blockIdx.x * 128;

    float acc[2][8][4];
    gemm_pipeline(sm, g_attg + p0 * CC, g_woutT, acc, t, lane, wm, wn);

    float* Cs = sm;
    store_acc_to_Cs(Cs, acc, lane, wm, wn);
    __syncthreads();

#pragma unroll
    for (int it = 0; it < 16; ++it) {
        int idx = it * 256 + t;                 // 4096 float4
        int j = idx >> 5, c4 = idx & 31;
        float4 v = *(float4*)(Cs + j * LDC + c4 * 4);
        float4 b = *(const float4*)(bout + c4 * 4);
        v.x += b.x; v.y += b.y; v.z += b.z; v.w += b.w;
        *(float4*)(out + (p0 + j) * CC + c4 * 4) = v;
    }
}

// ---------------------------------------------------------------------------
extern "C" void kernel_launch(void* const* d_in, const int* in_sizes, int n_in,
                              void* d_out, int out_size)
{
    const float* x2d   = (const float*)d_in[0];
    const float* ln_g  = (const float*)d_in[1];
    const float* ln_b  = (const float*)d_in[2];
    const float* Wqkv  = (const float*)d_in[3];
    const float* Wbias = (const float*)d_in[4];
    const float* Wgate = (const float*)d_in[5];
    const float* bgate = (const float*)d_in[6];
    const float* Wout  = (const float*)d_in[7];
    const float* bout  = (const float*)d_in[8];
    float* out = (float*)d_out;

    static bool attr_set = false;
    if (!attr_set) {
        cudaFuncSetAttribute(gemm512_kernel, cudaFuncAttributeMaxDynamicSharedMemorySize, GEMM_SMEM_BYTES);
        cudaFuncSetAttribute(gemm_out_kernel, cudaFuncAttributeMaxDynamicSharedMemorySize, GEMM_SMEM_BYTES);
        attr_set = true;
    }

    ln_kernel<<<NP / 8, 128>>>(x2d, ln_g, ln_b, Wbias);
    wprep_kernel<<<CC, 512>>>(Wqkv, Wgate);
    wprep2_kernel<<<CC, 128>>>(bgate, Wout);
    gemm512_kernel<<<dim3(512, 4), 256, GEMM_SMEM_BYTES>>>();
    phase2_kernel<<<dim3(2, NH, NN), 256>>>();
    gemm_out_kernel<<<512, 256, GEMM_SMEM_BYTES>>>(bout, out);
}